// round 10
// baseline (speedup 1.0000x reference)
#include <cuda_runtime.h>
#include <cstdint>

// ---------------------------------------------------------------------------
// Swin window-MSA, fp32.  GEMMs: smem-staged x + [k4][e][4] weights,
// 14 rows/thread k-pair FFMA2 (QTILE=112) -> weight-LDS amortized.
// Attention: 4 windows/block, single-pass softmax, split QK chains.
//   B=64, L=3136 (56x56), C=96, H=3, E=32, window 7x7 (49 tokens)
// ---------------------------------------------------------------------------

#define BATCH   64
#define IMG     56
#define WINSZ   7
#define NWIN    8
#define TOK     49
#define HEADS   3
#define CDIM    96
#define EDIM    32
#define LDIM    3136
#define MROWS   200704
#define WTOT    12288
#define QT      112
#define NROW    14

typedef unsigned long long u64;

__device__ __align__(16) float g_Q[WTOT * TOK * EDIM];
__device__ __align__(16) float g_K[WTOT * TOK * EDIM];
__device__ __align__(16) float g_V[WTOT * TOK * EDIM];
__device__ __align__(16) float g_AO[MROWS * CDIM];

// ---- packed f32x2 helpers ----
__device__ __forceinline__ u64 pack2(float a, float b) {
    u64 r;
    asm("mov.b64 %0, {%1, %2};" : "=l"(r) : "f"(a), "f"(b));
    return r;
}
__device__ __forceinline__ u64 fma2(u64 a, u64 b, u64 c) {
    u64 d;
    asm("fma.rn.f32x2 %0, %1, %2, %3;" : "=l"(d) : "l"(a), "l"(b), "l"(c));
    return d;
}
__device__ __forceinline__ float2 unpack2(u64 v) {
    float2 f;
    asm("mov.b64 {%0, %1}, %2;" : "=f"(f.x), "=f"(f.y) : "l"(v));
    return f;
}
__device__ __forceinline__ float hsum2(u64 v) {
    float2 f = unpack2(v);
    return f.x + f.y;
}

extern __shared__ float dsm[];

// smem layout (floats)
#define XS_FLOATS   (QT * 96 + 4)      // 10756
#define WPANEL      (24 * 128)          // [k4][e][4]

// ---------------------------------------------------------------------------
// Kernel 1: QKV GEMM + window scatter.
// grid (1792, 3), block 256.  Warp w owns rows [w*14, w*14+14).
// ---------------------------------------------------------------------------
__global__ void __launch_bounds__(256, 2) qkv_kernel(
    const float* __restrict__ x,
    const float* __restrict__ wqkv,
    const float* __restrict__ bqkv)
{
    float* xs = dsm;
    float* wq = dsm + XS_FLOATS;
    float* wk = wq + WPANEL;
    float* wv = wk + WPANEL;
    int*   rowdst = (int*)(wv + WPANEL);

    const int tile = blockIdx.x;
    const int h    = blockIdx.y;
    const int tid  = threadIdx.x;

    {
        const float4* xg = (const float4*)(x + (size_t)tile * (QT * 96));
        float4* xs4 = (float4*)xs;
        for (int i = tid; i < QT * 24; i += 256)
            xs4[i] = xg[i];
    }
    for (int t = tid; t < 96 * 96; t += 256) {
        int k = t / 96, j = t - k * 96;
        float val = wqkv[k * 288 + h * 96 + j];
        int e = j / 3, kk = j - e * 3;
        float* dst = (kk == 0) ? wq : (kk == 1) ? wk : wv;
        dst[(k >> 2) * 128 + e * 4 + (k & 3)] = val;
    }
    if (tid < QT) {
        int gr  = tile * QT + tid;
        int b   = gr / LDIM;
        int pix = gr - b * LDIM;
        int yy  = pix / IMG, xx = pix - yy * IMG;
        int win = (yy / WINSZ) * NWIN + (xx / WINSZ);
        int tok = (yy % WINSZ) * WINSZ + (xx % WINSZ);
        rowdst[tid] = (((b * HEADS + h) * (NWIN * NWIN) + win) * TOK + tok) * EDIM;
    }
    __syncthreads();

    const int e    = tid & 31;
    const int warp = tid >> 5;
    const int r0   = warp * NROW;
    const float bq = bqkv[h * 96 + e * 3 + 0];
    const float bk = bqkv[h * 96 + e * 3 + 1];
    const float bv = bqkv[h * 96 + e * 3 + 2];
    const float* wqe = wq + e * 4;
    const float* wke = wk + e * 4;
    const float* wve = wv + e * 4;
    const float* xb  = xs + r0 * 96;

    u64 aq[NROW], ak[NROW], av[NROW];
    #pragma unroll
    for (int r = 0; r < NROW; r++) {
        aq[r] = pack2(bq, 0.f);
        ak[r] = pack2(bk, 0.f);
        av[r] = pack2(bv, 0.f);
    }

    #pragma unroll 2
    for (int k4 = 0; k4 < 24; k4++) {
        ulonglong2 wqv = *(const ulonglong2*)(wqe + k4 * 128);
        ulonglong2 wkv = *(const ulonglong2*)(wke + k4 * 128);
        ulonglong2 wvv = *(const ulonglong2*)(wve + k4 * 128);
        #pragma unroll
        for (int r = 0; r < NROW; r++) {
            ulonglong2 xr = *(const ulonglong2*)(xb + r * 96 + k4 * 4);
            aq[r] = fma2(xr.x, wqv.x, aq[r]);
            aq[r] = fma2(xr.y, wqv.y, aq[r]);
            ak[r] = fma2(xr.x, wkv.x, ak[r]);
            ak[r] = fma2(xr.y, wkv.y, ak[r]);
            av[r] = fma2(xr.x, wvv.x, av[r]);
            av[r] = fma2(xr.y, wvv.y, av[r]);
        }
    }

    #pragma unroll
    for (int r = 0; r < NROW; r++) {
        int d = rowdst[r0 + r] + e;
        g_Q[d] = hsum2(aq[r]);
        g_K[d] = hsum2(ak[r]);
        g_V[d] = hsum2(av[r]);
    }
}

// ---------------------------------------------------------------------------
// Kernel 2: per-window attention, 4 windows per 256-thread block.
// Single fused pass: score (2 acc chains) -> exp -> sum -> PV accumulate.
// ---------------------------------------------------------------------------
__global__ void __launch_bounds__(256) attn_kernel(const float* __restrict__ rel_bias)
{
    float* Ks = dsm;                          // [4][49*32]
    float* Vs = Ks + 4 * TOK * EDIM;          // [4][49*32]
    float* Bs = Vs + 4 * TOK * EDIM;          // [49*49]

    const int tid  = threadIdx.x;
    const int part = tid >> 6;
    const int t    = tid & 63;
    const int widx = blockIdx.x * 4 + part;

    {
        const float4* kb = (const float4*)(g_K + (size_t)widx * (TOK * EDIM));
        const float4* vb = (const float4*)(g_V + (size_t)widx * (TOK * EDIM));
        float4* Ks4 = (float4*)(Ks + part * (TOK * EDIM));
        float4* Vs4 = (float4*)(Vs + part * (TOK * EDIM));
        for (int i = t; i < 392; i += 64) {
            Ks4[i] = kb[i];
            Vs4[i] = vb[i];
        }
    }
    for (int i = tid; i < TOK * TOK; i += 256) Bs[i] = rel_bias[i];
    __syncthreads();

    if (t < TOK) {
        const float* qb = g_Q + (size_t)widx * (TOK * EDIM) + t * EDIM;
        u64 qq[16];
        #pragma unroll
        for (int p = 0; p < 8; p++) {
            ulonglong2 qv = ((const ulonglong2*)qb)[p];
            qq[2 * p] = qv.x; qq[2 * p + 1] = qv.y;
        }

        const float scale = 0.17677669529663687f;  // 1/sqrt(32)
        const float* Kh = Ks + part * (TOK * EDIM);
        const float* Vh = Vs + part * (TOK * EDIM);
        const float* br = Bs + t * TOK;

        float sum = 0.f;
        u64 oo[16];
        #pragma unroll
        for (int p = 0; p < 16; p++) oo[p] = 0ull;

        #pragma unroll 7
        for (int j = 0; j < TOK; j++) {
            const ulonglong2* kr = (const ulonglong2*)(Kh + j * EDIM);
            u64 acc0 = 0ull, acc1 = 0ull;
            #pragma unroll
            for (int p = 0; p < 8; p++) {
                ulonglong2 kv = kr[p];
                acc0 = fma2(qq[2 * p], kv.x, acc0);
                acc1 = fma2(qq[2 * p + 1], kv.y, acc1);
            }
            float p = __expf((hsum2(acc0) + hsum2(acc1)) * scale + br[j]);
            sum += p;
            u64 pd = pack2(p, p);
            const ulonglong2* vr = (const ulonglong2*)(Vh + j * EDIM);
            #pragma unroll
            for (int u = 0; u < 8; u++) {
                ulonglong2 vv = vr[u];
                oo[2 * u]     = fma2(pd, vv.x, oo[2 * u]);
                oo[2 * u + 1] = fma2(pd, vv.y, oo[2 * u + 1]);
            }
        }
        float inv = 1.0f / sum;

        int b   = widx / (HEADS * NWIN * NWIN);
        int rem = widx - b * (HEADS * NWIN * NWIN);
        int h   = rem / (NWIN * NWIN);
        int win = rem - h * (NWIN * NWIN);
        int yy  = (win / NWIN) * WINSZ + t / WINSZ;
        int xx  = (win % NWIN) * WINSZ + t % WINSZ;
        float* dst = g_AO + ((size_t)b * LDIM + yy * IMG + xx) * CDIM + h * EDIM;
        #pragma unroll
        for (int u = 0; u < 8; u++) {
            float2 lo = unpack2(oo[2 * u]);
            float2 hi = unpack2(oo[2 * u + 1]);
            ((float4*)dst)[u] = make_float4(lo.x * inv, lo.y * inv,
                                            hi.x * inv, hi.y * inv);
        }
    }
}

// ---------------------------------------------------------------------------
// Kernel 3: output projection GEMM.  Same 14-rows/thread skeleton as K1.
// Thread (e, warp): columns {e, e+32, e+64}, rows [warp*14, warp*14+14).
// ---------------------------------------------------------------------------
__global__ void __launch_bounds__(256, 2) proj_kernel(
    const float* __restrict__ wproj,
    const float* __restrict__ bproj,
    float* __restrict__ out)
{
    float* xs = dsm;
    float* w0 = dsm + XS_FLOATS;
    float* w1 = w0 + WPANEL;
    float* w2 = w1 + WPANEL;

    const int tile = blockIdx.x;
    const int tid  = threadIdx.x;

    {
        const float4* xg = (const float4*)(g_AO + (size_t)tile * (QT * 96));
        float4* xs4 = (float4*)xs;
        for (int i = tid; i < QT * 24; i += 256)
            xs4[i] = xg[i];
    }
    for (int t = tid; t < 96 * 96; t += 256) {
        int k = t / 96, c = t - k * 96;
        int j = c >> 5, e2 = c & 31;
        float* dst = (j == 0) ? w0 : (j == 1) ? w1 : w2;
        dst[(k >> 2) * 128 + e2 * 4 + (k & 3)] = wproj[t];
    }
    __syncthreads();

    const int e    = tid & 31;
    const int warp = tid >> 5;
    const int r0   = warp * NROW;
    const float b0 = bproj[e];
    const float b1 = bproj[32 + e];
    const float b2 = bproj[64 + e];
    const float* w0e = w0 + e * 4;
    const float* w1e = w1 + e * 4;
    const float* w2e = w2 + e * 4;
    const float* xb  = xs + r0 * 96;

    u64 a0[NROW], a1[NROW], a2[NROW];
    #pragma unroll
    for (int r = 0; r < NROW; r++) {
        a0[r] = pack2(b0, 0.f);
        a1[r] = pack2(b1, 0.f);
        a2[r] = pack2(b2, 0.f);
    }

    #pragma unroll 2
    for (int k4 = 0; k4 < 24; k4++) {
        ulonglong2 w0v = *(const ulonglong2*)(w0e + k4 * 128);
        ulonglong2 w1v = *(const ulonglong2*)(w1e + k4 * 128);
        ulonglong2 w2v = *(const ulonglong2*)(w2e + k4 * 128);
        #pragma unroll
        for (int r = 0; r < NROW; r++) {
            ulonglong2 xr = *(const ulonglong2*)(xb + r * 96 + k4 * 4);
            a0[r] = fma2(xr.x, w0v.x, a0[r]);
            a0[r] = fma2(xr.y, w0v.y, a0[r]);
            a1[r] = fma2(xr.x, w1v.x, a1[r]);
            a1[r] = fma2(xr.y, w1v.y, a1[r]);
            a2[r] = fma2(xr.x, w2v.x, a2[r]);
            a2[r] = fma2(xr.y, w2v.y, a2[r]);
        }
    }

    float* ob = out + ((size_t)tile * QT + r0) * 96;
    #pragma unroll
    for (int r = 0; r < NROW; r++) {
        int o = r * 96;
        ob[o + e]      = hsum2(a0[r]);
        ob[o + 32 + e] = hsum2(a1[r]);
        ob[o + 64 + e] = hsum2(a2[r]);
    }
}

// ---------------------------------------------------------------------------
extern "C" void kernel_launch(void* const* d_in, const int* in_sizes, int n_in,
                              void* d_out, int out_size)
{
    (void)in_sizes; (void)n_in; (void)out_size;
    const float* x        = (const float*)d_in[0];
    const float* w_qkv    = (const float*)d_in[1];
    const float* b_qkv    = (const float*)d_in[2];
    const float* w_proj   = (const float*)d_in[3];
    const float* b_proj   = (const float*)d_in[4];
    const float* rel_bias = (const float*)d_in[5];
    float* out = (float*)d_out;

    const int qkv_smem  = (XS_FLOATS + 3 * WPANEL + QT) * 4;
    const int proj_smem = (XS_FLOATS + 3 * WPANEL) * 4;
    const int attn_smem = (8 * TOK * EDIM + TOK * TOK) * 4;   // 59.8 KB
    cudaFuncSetAttribute(qkv_kernel,  cudaFuncAttributeMaxDynamicSharedMemorySize, qkv_smem);
    cudaFuncSetAttribute(proj_kernel, cudaFuncAttributeMaxDynamicSharedMemorySize, proj_smem);
    cudaFuncSetAttribute(attn_kernel, cudaFuncAttributeMaxDynamicSharedMemorySize, attn_smem);

    qkv_kernel<<<dim3(MROWS / QT, 3), 256, qkv_smem>>>(x, w_qkv, b_qkv);
    attn_kernel<<<WTOT / 4, 256, attn_smem>>>(rel_bias);
    proj_kernel<<<MROWS / QT, 256, proj_smem>>>(w_proj, b_proj, out);
}

// round 11
// speedup vs baseline: 1.0656x; 1.0656x over previous
#include <cuda_runtime.h>
#include <cstdint>

// ---------------------------------------------------------------------------
// Swin window-MSA, fp32.  GEMMs: QT=64 single-pass, 8 rows/thread k-pair
// FFMA2, 3 blocks/SM (occupancy raise).  Attention: 2 win/block, 5 blocks/SM,
// single-pass softmax with split QK chains.
//   B=64, L=3136 (56x56), C=96, H=3, E=32, window 7x7 (49 tokens)
// ---------------------------------------------------------------------------

#define BATCH   64
#define IMG     56
#define WINSZ   7
#define NWIN    8
#define TOK     49
#define HEADS   3
#define CDIM    96
#define EDIM    32
#define LDIM    3136
#define MROWS   200704
#define WTOT    12288
#define QT      64
#define NROW    8

typedef unsigned long long u64;

__device__ __align__(16) float g_Q[WTOT * TOK * EDIM];
__device__ __align__(16) float g_K[WTOT * TOK * EDIM];
__device__ __align__(16) float g_V[WTOT * TOK * EDIM];
__device__ __align__(16) float g_AO[MROWS * CDIM];

// ---- packed f32x2 helpers ----
__device__ __forceinline__ u64 pack2(float a, float b) {
    u64 r;
    asm("mov.b64 %0, {%1, %2};" : "=l"(r) : "f"(a), "f"(b));
    return r;
}
__device__ __forceinline__ u64 fma2(u64 a, u64 b, u64 c) {
    u64 d;
    asm("fma.rn.f32x2 %0, %1, %2, %3;" : "=l"(d) : "l"(a), "l"(b), "l"(c));
    return d;
}
__device__ __forceinline__ float2 unpack2(u64 v) {
    float2 f;
    asm("mov.b64 {%0, %1}, %2;" : "=f"(f.x), "=f"(f.y) : "l"(v));
    return f;
}
__device__ __forceinline__ float hsum2(u64 v) {
    float2 f = unpack2(v);
    return f.x + f.y;
}

extern __shared__ float dsm[];

// smem layout (floats)
#define XS_FLOATS   (QT * 96 + 4)      // 6148
#define WPANEL      (24 * 128)          // [k4][e][4]

// ---------------------------------------------------------------------------
// Kernel 1: QKV GEMM + window scatter.
// grid (3136, 3), block 256.  Warp w owns rows [w*8, w*8+8), single pass.
// ---------------------------------------------------------------------------
__global__ void __launch_bounds__(256, 3) qkv_kernel(
    const float* __restrict__ x,
    const float* __restrict__ wqkv,
    const float* __restrict__ bqkv)
{
    float* xs = dsm;
    float* wq = dsm + XS_FLOATS;
    float* wk = wq + WPANEL;
    float* wv = wk + WPANEL;
    int*   rowdst = (int*)(wv + WPANEL);

    const int tile = blockIdx.x;
    const int h    = blockIdx.y;
    const int tid  = threadIdx.x;

    {
        const float4* xg = (const float4*)(x + (size_t)tile * (QT * 96));
        float4* xs4 = (float4*)xs;
        #pragma unroll
        for (int i = 0; i < (QT * 24) / 256; i++)
            xs4[tid + i * 256] = xg[tid + i * 256];
    }
    for (int t = tid; t < 96 * 96; t += 256) {
        int k = t / 96, j = t - k * 96;
        float val = wqkv[k * 288 + h * 96 + j];
        int e = j / 3, kk = j - e * 3;
        float* dst = (kk == 0) ? wq : (kk == 1) ? wk : wv;
        dst[(k >> 2) * 128 + e * 4 + (k & 3)] = val;
    }
    if (tid < QT) {
        int gr  = tile * QT + tid;
        int b   = gr / LDIM;
        int pix = gr - b * LDIM;
        int yy  = pix / IMG, xx = pix - yy * IMG;
        int win = (yy / WINSZ) * NWIN + (xx / WINSZ);
        int tok = (yy % WINSZ) * WINSZ + (xx % WINSZ);
        rowdst[tid] = (((b * HEADS + h) * (NWIN * NWIN) + win) * TOK + tok) * EDIM;
    }
    __syncthreads();

    const int e    = tid & 31;
    const int warp = tid >> 5;
    const int r0   = warp * NROW;
    const float bq = bqkv[h * 96 + e * 3 + 0];
    const float bk = bqkv[h * 96 + e * 3 + 1];
    const float bv = bqkv[h * 96 + e * 3 + 2];
    const float* wqe = wq + e * 4;
    const float* wke = wk + e * 4;
    const float* wve = wv + e * 4;
    const float* xb  = xs + r0 * 96;

    u64 aq[NROW], ak[NROW], av[NROW];
    #pragma unroll
    for (int r = 0; r < NROW; r++) {
        aq[r] = pack2(bq, 0.f);
        ak[r] = pack2(bk, 0.f);
        av[r] = pack2(bv, 0.f);
    }

    #pragma unroll 2
    for (int k4 = 0; k4 < 24; k4++) {
        ulonglong2 wqv = *(const ulonglong2*)(wqe + k4 * 128);
        ulonglong2 wkv = *(const ulonglong2*)(wke + k4 * 128);
        ulonglong2 wvv = *(const ulonglong2*)(wve + k4 * 128);
        #pragma unroll
        for (int r = 0; r < NROW; r++) {
            ulonglong2 xr = *(const ulonglong2*)(xb + r * 96 + k4 * 4);
            aq[r] = fma2(xr.x, wqv.x, aq[r]);
            aq[r] = fma2(xr.y, wqv.y, aq[r]);
            ak[r] = fma2(xr.x, wkv.x, ak[r]);
            ak[r] = fma2(xr.y, wkv.y, ak[r]);
            av[r] = fma2(xr.x, wvv.x, av[r]);
            av[r] = fma2(xr.y, wvv.y, av[r]);
        }
    }

    #pragma unroll
    for (int r = 0; r < NROW; r++) {
        int d = rowdst[r0 + r] + e;
        g_Q[d] = hsum2(aq[r]);
        g_K[d] = hsum2(ak[r]);
        g_V[d] = hsum2(av[r]);
    }
}

// ---------------------------------------------------------------------------
// Kernel 2: per-window attention, 2 windows per 128-thread block, 5 blocks/SM.
// Single fused pass: score (2 acc chains) -> exp -> sum -> PV accumulate.
// ---------------------------------------------------------------------------
__global__ void __launch_bounds__(128, 5) attn_kernel(const float* __restrict__ rel_bias)
{
    __shared__ __align__(16) float Ks[2][TOK * EDIM];
    __shared__ __align__(16) float Vs[2][TOK * EDIM];
    __shared__ float Bs[TOK * TOK];

    const int tid  = threadIdx.x;
    const int half = tid >> 6;
    const int t    = tid & 63;
    const int widx = blockIdx.x * 2 + half;

    {
        const float4* kb = (const float4*)(g_K + (size_t)widx * (TOK * EDIM));
        const float4* vb = (const float4*)(g_V + (size_t)widx * (TOK * EDIM));
        float4* Ks4 = (float4*)Ks[half];
        float4* Vs4 = (float4*)Vs[half];
        for (int i = t; i < 392; i += 64) {
            Ks4[i] = kb[i];
            Vs4[i] = vb[i];
        }
    }
    for (int i = tid; i < TOK * TOK; i += 128) Bs[i] = rel_bias[i];
    __syncthreads();

    if (t < TOK) {
        const float* qb = g_Q + (size_t)widx * (TOK * EDIM) + t * EDIM;
        u64 qq[16];
        #pragma unroll
        for (int p = 0; p < 8; p++) {
            ulonglong2 qv = ((const ulonglong2*)qb)[p];
            qq[2 * p] = qv.x; qq[2 * p + 1] = qv.y;
        }

        const float scale = 0.17677669529663687f;  // 1/sqrt(32)
        const float* Kh = Ks[half];
        const float* Vh = Vs[half];
        const float* br = Bs + t * TOK;

        float sum = 0.f;
        u64 oo[16];
        #pragma unroll
        for (int p = 0; p < 16; p++) oo[p] = 0ull;

        #pragma unroll 7
        for (int j = 0; j < TOK; j++) {
            const ulonglong2* kr = (const ulonglong2*)(Kh + j * EDIM);
            u64 acc0 = 0ull, acc1 = 0ull;
            #pragma unroll
            for (int p = 0; p < 8; p++) {
                ulonglong2 kv = kr[p];
                acc0 = fma2(qq[2 * p], kv.x, acc0);
                acc1 = fma2(qq[2 * p + 1], kv.y, acc1);
            }
            float p = __expf((hsum2(acc0) + hsum2(acc1)) * scale + br[j]);
            sum += p;
            u64 pd = pack2(p, p);
            const ulonglong2* vr = (const ulonglong2*)(Vh + j * EDIM);
            #pragma unroll
            for (int u = 0; u < 8; u++) {
                ulonglong2 vv = vr[u];
                oo[2 * u]     = fma2(pd, vv.x, oo[2 * u]);
                oo[2 * u + 1] = fma2(pd, vv.y, oo[2 * u + 1]);
            }
        }
        float inv = 1.0f / sum;

        int b   = widx / (HEADS * NWIN * NWIN);
        int rem = widx - b * (HEADS * NWIN * NWIN);
        int h   = rem / (NWIN * NWIN);
        int win = rem - h * (NWIN * NWIN);
        int yy  = (win / NWIN) * WINSZ + t / WINSZ;
        int xx  = (win % NWIN) * WINSZ + t % WINSZ;
        float* dst = g_AO + ((size_t)b * LDIM + yy * IMG + xx) * CDIM + h * EDIM;
        #pragma unroll
        for (int u = 0; u < 8; u++) {
            float2 lo = unpack2(oo[2 * u]);
            float2 hi = unpack2(oo[2 * u + 1]);
            ((float4*)dst)[u] = make_float4(lo.x * inv, lo.y * inv,
                                            hi.x * inv, hi.y * inv);
        }
    }
}

// ---------------------------------------------------------------------------
// Kernel 3: output projection GEMM.  Same QT=64 single-pass skeleton as K1.
// Thread (e, warp): columns {e, e+32, e+64}, rows [warp*8, warp*8+8).
// ---------------------------------------------------------------------------
__global__ void __launch_bounds__(256, 3) proj_kernel(
    const float* __restrict__ wproj,
    const float* __restrict__ bproj,
    float* __restrict__ out)
{
    float* xs = dsm;
    float* w0 = dsm + XS_FLOATS;
    float* w1 = w0 + WPANEL;
    float* w2 = w1 + WPANEL;

    const int tile = blockIdx.x;
    const int tid  = threadIdx.x;

    {
        const float4* xg = (const float4*)(g_AO + (size_t)tile * (QT * 96));
        float4* xs4 = (float4*)xs;
        #pragma unroll
        for (int i = 0; i < (QT * 24) / 256; i++)
            xs4[tid + i * 256] = xg[tid + i * 256];
    }
    for (int t = tid; t < 96 * 96; t += 256) {
        int k = t / 96, c = t - k * 96;
        int j = c >> 5, e2 = c & 31;
        float* dst = (j == 0) ? w0 : (j == 1) ? w1 : w2;
        dst[(k >> 2) * 128 + e2 * 4 + (k & 3)] = wproj[t];
    }
    __syncthreads();

    const int e    = tid & 31;
    const int warp = tid >> 5;
    const int r0   = warp * NROW;
    const float b0 = bproj[e];
    const float b1 = bproj[32 + e];
    const float b2 = bproj[64 + e];
    const float* w0e = w0 + e * 4;
    const float* w1e = w1 + e * 4;
    const float* w2e = w2 + e * 4;
    const float* xb  = xs + r0 * 96;

    u64 a0[NROW], a1[NROW], a2[NROW];
    #pragma unroll
    for (int r = 0; r < NROW; r++) {
        a0[r] = pack2(b0, 0.f);
        a1[r] = pack2(b1, 0.f);
        a2[r] = pack2(b2, 0.f);
    }

    #pragma unroll 2
    for (int k4 = 0; k4 < 24; k4++) {
        ulonglong2 w0v = *(const ulonglong2*)(w0e + k4 * 128);
        ulonglong2 w1v = *(const ulonglong2*)(w1e + k4 * 128);
        ulonglong2 w2v = *(const ulonglong2*)(w2e + k4 * 128);
        #pragma unroll
        for (int r = 0; r < NROW; r++) {
            ulonglong2 xr = *(const ulonglong2*)(xb + r * 96 + k4 * 4);
            a0[r] = fma2(xr.x, w0v.x, a0[r]);
            a0[r] = fma2(xr.y, w0v.y, a0[r]);
            a1[r] = fma2(xr.x, w1v.x, a1[r]);
            a1[r] = fma2(xr.y, w1v.y, a1[r]);
            a2[r] = fma2(xr.x, w2v.x, a2[r]);
            a2[r] = fma2(xr.y, w2v.y, a2[r]);
        }
    }

    float* ob = out + ((size_t)tile * QT + r0) * 96;
    #pragma unroll
    for (int r = 0; r < NROW; r++) {
        int o = r * 96;
        ob[o + e]      = hsum2(a0[r]);
        ob[o + 32 + e] = hsum2(a1[r]);
        ob[o + 64 + e] = hsum2(a2[r]);
    }
}

// ---------------------------------------------------------------------------
extern "C" void kernel_launch(void* const* d_in, const int* in_sizes, int n_in,
                              void* d_out, int out_size)
{
    (void)in_sizes; (void)n_in; (void)out_size;
    const float* x        = (const float*)d_in[0];
    const float* w_qkv    = (const float*)d_in[1];
    const float* b_qkv    = (const float*)d_in[2];
    const float* w_proj   = (const float*)d_in[3];
    const float* b_proj   = (const float*)d_in[4];
    const float* rel_bias = (const float*)d_in[5];
    float* out = (float*)d_out;

    const int qkv_smem  = (XS_FLOATS + 3 * WPANEL + QT) * 4;
    const int proj_smem = (XS_FLOATS + 3 * WPANEL) * 4;
    cudaFuncSetAttribute(qkv_kernel,  cudaFuncAttributeMaxDynamicSharedMemorySize, qkv_smem);
    cudaFuncSetAttribute(proj_kernel, cudaFuncAttributeMaxDynamicSharedMemorySize, proj_smem);

    qkv_kernel<<<dim3(MROWS / QT, 3), 256, qkv_smem>>>(x, w_qkv, b_qkv);
    attn_kernel<<<WTOT / 2, 128>>>(rel_bias);
    proj_kernel<<<MROWS / QT, 256, proj_smem>>>(w_proj, b_proj, out);
}

// round 12
// speedup vs baseline: 1.1914x; 1.1181x over previous
#include <cuda_runtime.h>
#include <cstdint>

// ---------------------------------------------------------------------------
// Swin window-MSA, fp32.  Prep kernel pre-transposes weights into the
// [k4][e][4] smem layout; GEMM blocks stage via pure float4 copies (no ALU).
// GEMMs: QT=64 single-pass, 8 rows/thread k-pair FFMA2, 3 blocks/SM.
// Attention: 2 win/block, 5 blocks/SM, single-pass softmax, split QK chains.
//   B=64, L=3136 (56x56), C=96, H=3, E=32, window 7x7 (49 tokens)
// ---------------------------------------------------------------------------

#define BATCH   64
#define IMG     56
#define WINSZ   7
#define NWIN    8
#define TOK     49
#define HEADS   3
#define CDIM    96
#define EDIM    32
#define LDIM    3136
#define MROWS   200704
#define WTOT    12288
#define QT      64
#define NROW    8

typedef unsigned long long u64;

__device__ __align__(16) float g_Q[WTOT * TOK * EDIM];
__device__ __align__(16) float g_K[WTOT * TOK * EDIM];
__device__ __align__(16) float g_V[WTOT * TOK * EDIM];
__device__ __align__(16) float g_AO[MROWS * CDIM];
// pre-transposed weights: qkv [head][mat][k4][e][4] ; proj [j][k4][e][4]
__device__ __align__(16) float g_Wqkv[3 * 3 * 3072];
__device__ __align__(16) float g_Wproj[3 * 3072];

// ---- packed f32x2 helpers ----
__device__ __forceinline__ u64 pack2(float a, float b) {
    u64 r;
    asm("mov.b64 %0, {%1, %2};" : "=l"(r) : "f"(a), "f"(b));
    return r;
}
__device__ __forceinline__ u64 fma2(u64 a, u64 b, u64 c) {
    u64 d;
    asm("fma.rn.f32x2 %0, %1, %2, %3;" : "=l"(d) : "l"(a), "l"(b), "l"(c));
    return d;
}
__device__ __forceinline__ float2 unpack2(u64 v) {
    float2 f;
    asm("mov.b64 {%0, %1}, %2;" : "=f"(f.x), "=f"(f.y) : "l"(v));
    return f;
}
__device__ __forceinline__ float hsum2(u64 v) {
    float2 f = unpack2(v);
    return f.x + f.y;
}

extern __shared__ float dsm[];

// smem layout (floats)
#define XS_FLOATS   (QT * 96 + 4)      // 6148
#define WPANEL      3072                // [k4][e][4] = 24*32*4

// ---------------------------------------------------------------------------
// Kernel 0: weight transpose prep (runs once, one block).
// ---------------------------------------------------------------------------
__global__ void __launch_bounds__(256) prep_kernel(
    const float* __restrict__ wqkv,
    const float* __restrict__ wproj)
{
    const int tid = threadIdx.x;
    // wqkv[k][c], c = h*96 + e*3 + mat  ->  g_Wqkv[(h*3+mat)*3072 + (k>>2)*128 + e*4 + (k&3)]
    for (int s = tid; s < 96 * 288; s += 256) {
        int k = s / 288, c = s - k * 288;
        int h = c / 96,  j = c - h * 96;
        int e = j / 3,   mat = j - e * 3;
        g_Wqkv[(h * 3 + mat) * 3072 + (k >> 2) * 128 + e * 4 + (k & 3)] = wqkv[s];
    }
    // wproj[k][c], c = j*32 + e  ->  g_Wproj[j*3072 + (k>>2)*128 + e*4 + (k&3)]
    for (int s = tid; s < 96 * 96; s += 256) {
        int k = s / 96, c = s - k * 96;
        int j = c >> 5, e = c & 31;
        g_Wproj[j * 3072 + (k >> 2) * 128 + e * 4 + (k & 3)] = wproj[s];
    }
}

// ---------------------------------------------------------------------------
// Kernel 1: QKV GEMM + window scatter.
// grid (3136, 3), block 256, 3 blocks/SM.  Warp w owns rows [w*8, w*8+8).
// ---------------------------------------------------------------------------
__global__ void __launch_bounds__(256, 3) qkv_kernel(
    const float* __restrict__ x,
    const float* __restrict__ bqkv)
{
    float* xs = dsm;
    float* ws = dsm + XS_FLOATS;          // wq | wk | wv contiguous (3*3072)
    int*   rowdst = (int*)(ws + 3 * WPANEL);

    const int tile = blockIdx.x;
    const int h    = blockIdx.y;
    const int tid  = threadIdx.x;

    // stage x tile: 64*24 = 1536 float4
    {
        const float4* xg = (const float4*)(x + (size_t)tile * (QT * 96));
        float4* xs4 = (float4*)xs;
        #pragma unroll
        for (int i = 0; i < (QT * 24) / 256; i++)
            xs4[tid + i * 256] = xg[tid + i * 256];
    }
    // stage weights: pure copy of 9216 floats = 2304 float4
    {
        const float4* wg = (const float4*)(g_Wqkv + h * 3 * WPANEL);
        float4* wsm = (float4*)ws;
        #pragma unroll
        for (int i = 0; i < (3 * WPANEL) / 4 / 256; i++)
            wsm[tid + i * 256] = wg[tid + i * 256];
    }
    if (tid < QT) {
        int gr  = tile * QT + tid;
        int b   = gr / LDIM;
        int pix = gr - b * LDIM;
        int yy  = pix / IMG, xx = pix - yy * IMG;
        int win = (yy / WINSZ) * NWIN + (xx / WINSZ);
        int tok = (yy % WINSZ) * WINSZ + (xx % WINSZ);
        rowdst[tid] = (((b * HEADS + h) * (NWIN * NWIN) + win) * TOK + tok) * EDIM;
    }
    __syncthreads();

    const int e    = tid & 31;
    const int warp = tid >> 5;
    const int r0   = warp * NROW;
    const float bq = bqkv[h * 96 + e * 3 + 0];
    const float bk = bqkv[h * 96 + e * 3 + 1];
    const float bv = bqkv[h * 96 + e * 3 + 2];
    const float* wqe = ws + e * 4;
    const float* wke = ws + WPANEL + e * 4;
    const float* wve = ws + 2 * WPANEL + e * 4;
    const float* xb  = xs + r0 * 96;

    u64 aq[NROW], ak[NROW], av[NROW];
    #pragma unroll
    for (int r = 0; r < NROW; r++) {
        aq[r] = pack2(bq, 0.f);
        ak[r] = pack2(bk, 0.f);
        av[r] = pack2(bv, 0.f);
    }

    #pragma unroll 2
    for (int k4 = 0; k4 < 24; k4++) {
        ulonglong2 wqv = *(const ulonglong2*)(wqe + k4 * 128);
        ulonglong2 wkv = *(const ulonglong2*)(wke + k4 * 128);
        ulonglong2 wvv = *(const ulonglong2*)(wve + k4 * 128);
        #pragma unroll
        for (int r = 0; r < NROW; r++) {
            ulonglong2 xr = *(const ulonglong2*)(xb + r * 96 + k4 * 4);
            aq[r] = fma2(xr.x, wqv.x, aq[r]);
            aq[r] = fma2(xr.y, wqv.y, aq[r]);
            ak[r] = fma2(xr.x, wkv.x, ak[r]);
            ak[r] = fma2(xr.y, wkv.y, ak[r]);
            av[r] = fma2(xr.x, wvv.x, av[r]);
            av[r] = fma2(xr.y, wvv.y, av[r]);
        }
    }

    #pragma unroll
    for (int r = 0; r < NROW; r++) {
        int d = rowdst[r0 + r] + e;
        g_Q[d] = hsum2(aq[r]);
        g_K[d] = hsum2(ak[r]);
        g_V[d] = hsum2(av[r]);
    }
}

// ---------------------------------------------------------------------------
// Kernel 2: per-window attention, 2 windows per 128-thread block, 5 blocks/SM.
// Single fused pass: score (2 acc chains) -> exp -> sum -> PV accumulate.
// ---------------------------------------------------------------------------
__global__ void __launch_bounds__(128, 5) attn_kernel(const float* __restrict__ rel_bias)
{
    __shared__ __align__(16) float Ks[2][TOK * EDIM];
    __shared__ __align__(16) float Vs[2][TOK * EDIM];
    __shared__ float Bs[TOK * TOK];

    const int tid  = threadIdx.x;
    const int half = tid >> 6;
    const int t    = tid & 63;
    const int widx = blockIdx.x * 2 + half;

    {
        const float4* kb = (const float4*)(g_K + (size_t)widx * (TOK * EDIM));
        const float4* vb = (const float4*)(g_V + (size_t)widx * (TOK * EDIM));
        float4* Ks4 = (float4*)Ks[half];
        float4* Vs4 = (float4*)Vs[half];
        for (int i = t; i < 392; i += 64) {
            Ks4[i] = kb[i];
            Vs4[i] = vb[i];
        }
    }
    for (int i = tid; i < TOK * TOK; i += 128) Bs[i] = rel_bias[i];
    __syncthreads();

    if (t < TOK) {
        const float* qb = g_Q + (size_t)widx * (TOK * EDIM) + t * EDIM;
        u64 qq[16];
        #pragma unroll
        for (int p = 0; p < 8; p++) {
            ulonglong2 qv = ((const ulonglong2*)qb)[p];
            qq[2 * p] = qv.x; qq[2 * p + 1] = qv.y;
        }

        const float scale = 0.17677669529663687f;  // 1/sqrt(32)
        const float* Kh = Ks[half];
        const float* Vh = Vs[half];
        const float* br = Bs + t * TOK;

        float sum = 0.f;
        u64 oo[16];
        #pragma unroll
        for (int p = 0; p < 16; p++) oo[p] = 0ull;

        #pragma unroll 7
        for (int j = 0; j < TOK; j++) {
            const ulonglong2* kr = (const ulonglong2*)(Kh + j * EDIM);
            u64 acc0 = 0ull, acc1 = 0ull;
            #pragma unroll
            for (int p = 0; p < 8; p++) {
                ulonglong2 kv = kr[p];
                acc0 = fma2(qq[2 * p], kv.x, acc0);
                acc1 = fma2(qq[2 * p + 1], kv.y, acc1);
            }
            float p = __expf((hsum2(acc0) + hsum2(acc1)) * scale + br[j]);
            sum += p;
            u64 pd = pack2(p, p);
            const ulonglong2* vr = (const ulonglong2*)(Vh + j * EDIM);
            #pragma unroll
            for (int u = 0; u < 8; u++) {
                ulonglong2 vv = vr[u];
                oo[2 * u]     = fma2(pd, vv.x, oo[2 * u]);
                oo[2 * u + 1] = fma2(pd, vv.y, oo[2 * u + 1]);
            }
        }
        float inv = 1.0f / sum;

        int b   = widx / (HEADS * NWIN * NWIN);
        int rem = widx - b * (HEADS * NWIN * NWIN);
        int h   = rem / (NWIN * NWIN);
        int win = rem - h * (NWIN * NWIN);
        int yy  = (win / NWIN) * WINSZ + t / WINSZ;
        int xx  = (win % NWIN) * WINSZ + t % WINSZ;
        float* dst = g_AO + ((size_t)b * LDIM + yy * IMG + xx) * CDIM + h * EDIM;
        #pragma unroll
        for (int u = 0; u < 8; u++) {
            float2 lo = unpack2(oo[2 * u]);
            float2 hi = unpack2(oo[2 * u + 1]);
            ((float4*)dst)[u] = make_float4(lo.x * inv, lo.y * inv,
                                            hi.x * inv, hi.y * inv);
        }
    }
}

// ---------------------------------------------------------------------------
// Kernel 3: output projection GEMM.  Same skeleton as K1, 3 blocks/SM.
// Thread (e, warp): columns {e, e+32, e+64}, rows [warp*8, warp*8+8).
// ---------------------------------------------------------------------------
__global__ void __launch_bounds__(256, 3) proj_kernel(
    const float* __restrict__ bproj,
    float* __restrict__ out)
{
    float* xs = dsm;
    float* ws = dsm + XS_FLOATS;   // w0 | w1 | w2 contiguous

    const int tile = blockIdx.x;
    const int tid  = threadIdx.x;

    {
        const float4* xg = (const float4*)(g_AO + (size_t)tile * (QT * 96));
        float4* xs4 = (float4*)xs;
        #pragma unroll
        for (int i = 0; i < (QT * 24) / 256; i++)
            xs4[tid + i * 256] = xg[tid + i * 256];
    }
    {
        const float4* wg = (const float4*)g_Wproj;
        float4* wsm = (float4*)ws;
        #pragma unroll
        for (int i = 0; i < (3 * WPANEL) / 4 / 256; i++)
            wsm[tid + i * 256] = wg[tid + i * 256];
    }
    __syncthreads();

    const int e    = tid & 31;
    const int warp = tid >> 5;
    const int r0   = warp * NROW;
    const float b0 = bproj[e];
    const float b1 = bproj[32 + e];
    const float b2 = bproj[64 + e];
    const float* w0e = ws + e * 4;
    const float* w1e = ws + WPANEL + e * 4;
    const float* w2e = ws + 2 * WPANEL + e * 4;
    const float* xb  = xs + r0 * 96;

    u64 a0[NROW], a1[NROW], a2[NROW];
    #pragma unroll
    for (int r = 0; r < NROW; r++) {
        a0[r] = pack2(b0, 0.f);
        a1[r] = pack2(b1, 0.f);
        a2[r] = pack2(b2, 0.f);
    }

    #pragma unroll 2
    for (int k4 = 0; k4 < 24; k4++) {
        ulonglong2 w0v = *(const ulonglong2*)(w0e + k4 * 128);
        ulonglong2 w1v = *(const ulonglong2*)(w1e + k4 * 128);
        ulonglong2 w2v = *(const ulonglong2*)(w2e + k4 * 128);
        #pragma unroll
        for (int r = 0; r < NROW; r++) {
            ulonglong2 xr = *(const ulonglong2*)(xb + r * 96 + k4 * 4);
            a0[r] = fma2(xr.x, w0v.x, a0[r]);
            a0[r] = fma2(xr.y, w0v.y, a0[r]);
            a1[r] = fma2(xr.x, w1v.x, a1[r]);
            a1[r] = fma2(xr.y, w1v.y, a1[r]);
            a2[r] = fma2(xr.x, w2v.x, a2[r]);
            a2[r] = fma2(xr.y, w2v.y, a2[r]);
        }
    }

    float* ob = out + ((size_t)tile * QT + r0) * 96;
    #pragma unroll
    for (int r = 0; r < NROW; r++) {
        int o = r * 96;
        ob[o + e]      = hsum2(a0[r]);
        ob[o + 32 + e] = hsum2(a1[r]);
        ob[o + 64 + e] = hsum2(a2[r]);
    }
}

// ---------------------------------------------------------------------------
extern "C" void kernel_launch(void* const* d_in, const int* in_sizes, int n_in,
                              void* d_out, int out_size)
{
    (void)in_sizes; (void)n_in; (void)out_size;
    const float* x        = (const float*)d_in[0];
    const float* w_qkv    = (const float*)d_in[1];
    const float* b_qkv    = (const float*)d_in[2];
    const float* w_proj   = (const float*)d_in[3];
    const float* b_proj   = (const float*)d_in[4];
    const float* rel_bias = (const float*)d_in[5];
    float* out = (float*)d_out;

    const int qkv_smem  = (XS_FLOATS + 3 * WPANEL) * 4 + QT * 4;
    const int proj_smem = (XS_FLOATS + 3 * WPANEL) * 4;
    cudaFuncSetAttribute(qkv_kernel,  cudaFuncAttributeMaxDynamicSharedMemorySize, qkv_smem);
    cudaFuncSetAttribute(proj_kernel, cudaFuncAttributeMaxDynamicSharedMemorySize, proj_smem);

    prep_kernel<<<1, 256>>>(w_qkv, w_proj);
    qkv_kernel<<<dim3(MROWS / QT, 3), 256, qkv_smem>>>(x, b_qkv);
    attn_kernel<<<WTOT / 2, 128>>>(rel_bias);
    proj_kernel<<<MROWS / QT, 256, proj_smem>>>(b_proj, out);
}

// round 13
// speedup vs baseline: 1.2244x; 1.0277x over previous
#include <cuda_runtime.h>
#include <cstdint>

// ---------------------------------------------------------------------------
// Swin window-MSA, fp32.  Best-of composition:
//  - prep kernel pre-transposes weights into [k4][e][4] (pure-copy staging)
//  - GEMMs: QT=128, 8 rows/warp x 2 passes, k-pair FFMA2 (R8 shape)
//  - attention: 2 win/block, 5 blocks/SM, single-pass softmax, split chains
//   B=64, L=3136 (56x56), C=96, H=3, E=32, window 7x7 (49 tokens)
// ---------------------------------------------------------------------------

#define BATCH   64
#define IMG     56
#define WINSZ   7
#define NWIN    8
#define TOK     49
#define HEADS   3
#define CDIM    96
#define EDIM    32
#define LDIM    3136
#define MROWS   200704
#define WTOT    12288
#define QT      128
#define NROW    8

typedef unsigned long long u64;

__device__ __align__(16) float g_Q[WTOT * TOK * EDIM];
__device__ __align__(16) float g_K[WTOT * TOK * EDIM];
__device__ __align__(16) float g_V[WTOT * TOK * EDIM];
__device__ __align__(16) float g_AO[MROWS * CDIM];
// pre-transposed weights: qkv [head][mat][k4][e][4] ; proj [j][k4][e][4]
__device__ __align__(16) float g_Wqkv[3 * 3 * 3072];
__device__ __align__(16) float g_Wproj[3 * 3072];

// ---- packed f32x2 helpers ----
__device__ __forceinline__ u64 pack2(float a, float b) {
    u64 r;
    asm("mov.b64 %0, {%1, %2};" : "=l"(r) : "f"(a), "f"(b));
    return r;
}
__device__ __forceinline__ u64 fma2(u64 a, u64 b, u64 c) {
    u64 d;
    asm("fma.rn.f32x2 %0, %1, %2, %3;" : "=l"(d) : "l"(a), "l"(b), "l"(c));
    return d;
}
__device__ __forceinline__ float2 unpack2(u64 v) {
    float2 f;
    asm("mov.b64 {%0, %1}, %2;" : "=f"(f.x), "=f"(f.y) : "l"(v));
    return f;
}
__device__ __forceinline__ float hsum2(u64 v) {
    float2 f = unpack2(v);
    return f.x + f.y;
}

extern __shared__ float dsm[];

// smem layout (floats)
#define XS_FLOATS   (QT * 96 + 4)      // 12292
#define WPANEL      3072                // [k4][e][4] = 24*32*4

// ---------------------------------------------------------------------------
// Kernel 0: weight transpose prep (runs once, one block).
// ---------------------------------------------------------------------------
__global__ void __launch_bounds__(256) prep_kernel(
    const float* __restrict__ wqkv,
    const float* __restrict__ wproj)
{
    const int tid = threadIdx.x;
    for (int s = tid; s < 96 * 288; s += 256) {
        int k = s / 288, c = s - k * 288;
        int h = c / 96,  j = c - h * 96;
        int e = j / 3,   mat = j - e * 3;
        g_Wqkv[(h * 3 + mat) * 3072 + (k >> 2) * 128 + e * 4 + (k & 3)] = wqkv[s];
    }
    for (int s = tid; s < 96 * 96; s += 256) {
        int k = s / 96, c = s - k * 96;
        int j = c >> 5, e = c & 31;
        g_Wproj[j * 3072 + (k >> 2) * 128 + e * 4 + (k & 3)] = wproj[s];
    }
}

// ---------------------------------------------------------------------------
// Kernel 1: QKV GEMM + window scatter.
// grid (1568, 3), block 256, 2 blocks/SM.  Warp w: rows w*8.. in 2 passes.
// ---------------------------------------------------------------------------
__global__ void __launch_bounds__(256, 2) qkv_kernel(
    const float* __restrict__ x,
    const float* __restrict__ bqkv)
{
    float* xs = dsm;
    float* ws = dsm + XS_FLOATS;          // wq | wk | wv contiguous (3*3072)
    int*   rowdst = (int*)(ws + 3 * WPANEL);

    const int tile = blockIdx.x;
    const int h    = blockIdx.y;
    const int tid  = threadIdx.x;

    // stage x tile: 128*24 = 3072 float4 (pure copy)
    {
        const float4* xg = (const float4*)(x + (size_t)tile * (QT * 96));
        float4* xs4 = (float4*)xs;
        #pragma unroll
        for (int i = 0; i < (QT * 24) / 256; i++)
            xs4[tid + i * 256] = xg[tid + i * 256];
    }
    // stage weights: pure copy of 9216 floats = 2304 float4
    {
        const float4* wg = (const float4*)(g_Wqkv + h * 3 * WPANEL);
        float4* wsm = (float4*)ws;
        #pragma unroll
        for (int i = 0; i < (3 * WPANEL) / 4 / 256; i++)
            wsm[tid + i * 256] = wg[tid + i * 256];
    }
    if (tid < QT) {
        int gr  = tile * QT + tid;
        int b   = gr / LDIM;
        int pix = gr - b * LDIM;
        int yy  = pix / IMG, xx = pix - yy * IMG;
        int win = (yy / WINSZ) * NWIN + (xx / WINSZ);
        int tok = (yy % WINSZ) * WINSZ + (xx % WINSZ);
        rowdst[tid] = (((b * HEADS + h) * (NWIN * NWIN) + win) * TOK + tok) * EDIM;
    }
    __syncthreads();

    const int e    = tid & 31;
    const int warp = tid >> 5;
    const float bq = bqkv[h * 96 + e * 3 + 0];
    const float bk = bqkv[h * 96 + e * 3 + 1];
    const float bv = bqkv[h * 96 + e * 3 + 2];
    const float* wqe = ws + e * 4;
    const float* wke = ws + WPANEL + e * 4;
    const float* wve = ws + 2 * WPANEL + e * 4;

    #pragma unroll 1
    for (int pass = 0; pass < 2; pass++) {
        const int r0 = pass * 64 + warp * NROW;
        const float* xb = xs + r0 * 96;

        u64 aq[NROW], ak[NROW], av[NROW];
        #pragma unroll
        for (int r = 0; r < NROW; r++) {
            aq[r] = pack2(bq, 0.f);
            ak[r] = pack2(bk, 0.f);
            av[r] = pack2(bv, 0.f);
        }

        #pragma unroll 2
        for (int k4 = 0; k4 < 24; k4++) {
            ulonglong2 wqv = *(const ulonglong2*)(wqe + k4 * 128);
            ulonglong2 wkv = *(const ulonglong2*)(wke + k4 * 128);
            ulonglong2 wvv = *(const ulonglong2*)(wve + k4 * 128);
            #pragma unroll
            for (int r = 0; r < NROW; r++) {
                ulonglong2 xr = *(const ulonglong2*)(xb + r * 96 + k4 * 4);
                aq[r] = fma2(xr.x, wqv.x, aq[r]);
                aq[r] = fma2(xr.y, wqv.y, aq[r]);
                ak[r] = fma2(xr.x, wkv.x, ak[r]);
                ak[r] = fma2(xr.y, wkv.y, ak[r]);
                av[r] = fma2(xr.x, wvv.x, av[r]);
                av[r] = fma2(xr.y, wvv.y, av[r]);
            }
        }

        #pragma unroll
        for (int r = 0; r < NROW; r++) {
            int d = rowdst[r0 + r] + e;
            g_Q[d] = hsum2(aq[r]);
            g_K[d] = hsum2(ak[r]);
            g_V[d] = hsum2(av[r]);
        }
    }
}

// ---------------------------------------------------------------------------
// Kernel 2: per-window attention, 2 windows per 128-thread block, 5 blocks/SM.
// ---------------------------------------------------------------------------
__global__ void __launch_bounds__(128, 5) attn_kernel(const float* __restrict__ rel_bias)
{
    __shared__ __align__(16) float Ks[2][TOK * EDIM];
    __shared__ __align__(16) float Vs[2][TOK * EDIM];
    __shared__ float Bs[TOK * TOK];

    const int tid  = threadIdx.x;
    const int half = tid >> 6;
    const int t    = tid & 63;
    const int widx = blockIdx.x * 2 + half;

    {
        const float4* kb = (const float4*)(g_K + (size_t)widx * (TOK * EDIM));
        const float4* vb = (const float4*)(g_V + (size_t)widx * (TOK * EDIM));
        float4* Ks4 = (float4*)Ks[half];
        float4* Vs4 = (float4*)Vs[half];
        for (int i = t; i < 392; i += 64) {
            Ks4[i] = kb[i];
            Vs4[i] = vb[i];
        }
    }
    for (int i = tid; i < TOK * TOK; i += 128) Bs[i] = rel_bias[i];
    __syncthreads();

    if (t < TOK) {
        const float* qb = g_Q + (size_t)widx * (TOK * EDIM) + t * EDIM;
        u64 qq[16];
        #pragma unroll
        for (int p = 0; p < 8; p++) {
            ulonglong2 qv = ((const ulonglong2*)qb)[p];
            qq[2 * p] = qv.x; qq[2 * p + 1] = qv.y;
        }

        const float scale = 0.17677669529663687f;  // 1/sqrt(32)
        const float* Kh = Ks[half];
        const float* Vh = Vs[half];
        const float* br = Bs + t * TOK;

        float sum = 0.f;
        u64 oo[16];
        #pragma unroll
        for (int p = 0; p < 16; p++) oo[p] = 0ull;

        #pragma unroll 7
        for (int j = 0; j < TOK; j++) {
            const ulonglong2* kr = (const ulonglong2*)(Kh + j * EDIM);
            u64 acc0 = 0ull, acc1 = 0ull;
            #pragma unroll
            for (int p = 0; p < 8; p++) {
                ulonglong2 kv = kr[p];
                acc0 = fma2(qq[2 * p], kv.x, acc0);
                acc1 = fma2(qq[2 * p + 1], kv.y, acc1);
            }
            float p = __expf((hsum2(acc0) + hsum2(acc1)) * scale + br[j]);
            sum += p;
            u64 pd = pack2(p, p);
            const ulonglong2* vr = (const ulonglong2*)(Vh + j * EDIM);
            #pragma unroll
            for (int u = 0; u < 8; u++) {
                ulonglong2 vv = vr[u];
                oo[2 * u]     = fma2(pd, vv.x, oo[2 * u]);
                oo[2 * u + 1] = fma2(pd, vv.y, oo[2 * u + 1]);
            }
        }
        float inv = 1.0f / sum;

        int b   = widx / (HEADS * NWIN * NWIN);
        int rem = widx - b * (HEADS * NWIN * NWIN);
        int h   = rem / (NWIN * NWIN);
        int win = rem - h * (NWIN * NWIN);
        int yy  = (win / NWIN) * WINSZ + t / WINSZ;
        int xx  = (win % NWIN) * WINSZ + t % WINSZ;
        float* dst = g_AO + ((size_t)b * LDIM + yy * IMG + xx) * CDIM + h * EDIM;
        #pragma unroll
        for (int u = 0; u < 8; u++) {
            float2 lo = unpack2(oo[2 * u]);
            float2 hi = unpack2(oo[2 * u + 1]);
            ((float4*)dst)[u] = make_float4(lo.x * inv, lo.y * inv,
                                            hi.x * inv, hi.y * inv);
        }
    }
}

// ---------------------------------------------------------------------------
// Kernel 3: output projection GEMM.  QT=128, 2 passes, pure-copy staging.
// Thread (e, warp): columns {e, e+32, e+64}.
// ---------------------------------------------------------------------------
__global__ void __launch_bounds__(256, 2) proj_kernel(
    const float* __restrict__ bproj,
    float* __restrict__ out)
{
    float* xs = dsm;
    float* ws = dsm + XS_FLOATS;   // w0 | w1 | w2 contiguous

    const int tile = blockIdx.x;
    const int tid  = threadIdx.x;

    {
        const float4* xg = (const float4*)(g_AO + (size_t)tile * (QT * 96));
        float4* xs4 = (float4*)xs;
        #pragma unroll
        for (int i = 0; i < (QT * 24) / 256; i++)
            xs4[tid + i * 256] = xg[tid + i * 256];
    }
    {
        const float4* wg = (const float4*)g_Wproj;
        float4* wsm = (float4*)ws;
        #pragma unroll
        for (int i = 0; i < (3 * WPANEL) / 4 / 256; i++)
            wsm[tid + i * 256] = wg[tid + i * 256];
    }
    __syncthreads();

    const int e    = tid & 31;
    const int warp = tid >> 5;
    const float b0 = bproj[e];
    const float b1 = bproj[32 + e];
    const float b2 = bproj[64 + e];
    const float* w0e = ws + e * 4;
    const float* w1e = ws + WPANEL + e * 4;
    const float* w2e = ws + 2 * WPANEL + e * 4;

    #pragma unroll 1
    for (int pass = 0; pass < 2; pass++) {
        const int r0 = pass * 64 + warp * NROW;
        const float* xb = xs + r0 * 96;

        u64 a0[NROW], a1[NROW], a2[NROW];
        #pragma unroll
        for (int r = 0; r < NROW; r++) {
            a0[r] = pack2(b0, 0.f);
            a1[r] = pack2(b1, 0.f);
            a2[r] = pack2(b2, 0.f);
        }

        #pragma unroll 2
        for (int k4 = 0; k4 < 24; k4++) {
            ulonglong2 w0v = *(const ulonglong2*)(w0e + k4 * 128);
            ulonglong2 w1v = *(const ulonglong2*)(w1e + k4 * 128);
            ulonglong2 w2v = *(const ulonglong2*)(w2e + k4 * 128);
            #pragma unroll
            for (int r = 0; r < NROW; r++) {
                ulonglong2 xr = *(const ulonglong2*)(xb + r * 96 + k4 * 4);
                a0[r] = fma2(xr.x, w0v.x, a0[r]);
                a0[r] = fma2(xr.y, w0v.y, a0[r]);
                a1[r] = fma2(xr.x, w1v.x, a1[r]);
                a1[r] = fma2(xr.y, w1v.y, a1[r]);
                a2[r] = fma2(xr.x, w2v.x, a2[r]);
                a2[r] = fma2(xr.y, w2v.y, a2[r]);
            }
        }

        float* ob = out + ((size_t)tile * QT + r0) * 96;
        #pragma unroll
        for (int r = 0; r < NROW; r++) {
            int o = r * 96;
            ob[o + e]      = hsum2(a0[r]);
            ob[o + 32 + e] = hsum2(a1[r]);
            ob[o + 64 + e] = hsum2(a2[r]);
        }
    }
}

// ---------------------------------------------------------------------------
extern "C" void kernel_launch(void* const* d_in, const int* in_sizes, int n_in,
                              void* d_out, int out_size)
{
    (void)in_sizes; (void)n_in; (void)out_size;
    const float* x        = (const float*)d_in[0];
    const float* w_qkv    = (const float*)d_in[1];
    const float* b_qkv    = (const float*)d_in[2];
    const float* w_proj   = (const float*)d_in[3];
    const float* b_proj   = (const float*)d_in[4];
    const float* rel_bias = (const float*)d_in[5];
    float* out = (float*)d_out;

    const int qkv_smem  = (XS_FLOATS + 3 * WPANEL + QT) * 4;
    const int proj_smem = (XS_FLOATS + 3 * WPANEL) * 4;
    cudaFuncSetAttribute(qkv_kernel,  cudaFuncAttributeMaxDynamicSharedMemorySize, qkv_smem);
    cudaFuncSetAttribute(proj_kernel, cudaFuncAttributeMaxDynamicSharedMemorySize, proj_smem);

    prep_kernel<<<1, 256>>>(w_qkv, w_proj);
    qkv_kernel<<<dim3(MROWS / QT, 3), 256, qkv_smem>>>(x, b_qkv);
    attn_kernel<<<WTOT / 2, 128>>>(rel_bias);
    proj_kernel<<<MROWS / QT, 256, proj_smem>>>(b_proj, out);
}

// round 14
// speedup vs baseline: 1.3058x; 1.0665x over previous
#include <cuda_runtime.h>
#include <cstdint>

// ---------------------------------------------------------------------------
// Swin window-MSA, fp32.  Measured-best composition:
//  - prep kernel pre-transposes weights into [k4][e][4] (pure-copy staging)
//  - GEMMs: QT=128, 8 rows/warp x 2 passes, k-pair FFMA2 (R8 loop shape)
//  - attention: R8 exact config (static smem, LB(128,4), single QK chain)
//   B=64, L=3136 (56x56), C=96, H=3, E=32, window 7x7 (49 tokens)
// ---------------------------------------------------------------------------

#define BATCH   64
#define IMG     56
#define WINSZ   7
#define NWIN    8
#define TOK     49
#define HEADS   3
#define CDIM    96
#define EDIM    32
#define LDIM    3136
#define MROWS   200704
#define WTOT    12288
#define QT      128
#define NROW    8

typedef unsigned long long u64;

__device__ __align__(16) float g_Q[WTOT * TOK * EDIM];
__device__ __align__(16) float g_K[WTOT * TOK * EDIM];
__device__ __align__(16) float g_V[WTOT * TOK * EDIM];
__device__ __align__(16) float g_AO[MROWS * CDIM];
// pre-transposed weights: qkv [head][mat][k4][e][4] ; proj [j][k4][e][4]
__device__ __align__(16) float g_Wqkv[3 * 3 * 3072];
__device__ __align__(16) float g_Wproj[3 * 3072];

// ---- packed f32x2 helpers ----
__device__ __forceinline__ u64 pack2(float a, float b) {
    u64 r;
    asm("mov.b64 %0, {%1, %2};" : "=l"(r) : "f"(a), "f"(b));
    return r;
}
__device__ __forceinline__ u64 fma2(u64 a, u64 b, u64 c) {
    u64 d;
    asm("fma.rn.f32x2 %0, %1, %2, %3;" : "=l"(d) : "l"(a), "l"(b), "l"(c));
    return d;
}
__device__ __forceinline__ float2 unpack2(u64 v) {
    float2 f;
    asm("mov.b64 {%0, %1}, %2;" : "=f"(f.x), "=f"(f.y) : "l"(v));
    return f;
}
__device__ __forceinline__ float hsum2(u64 v) {
    float2 f = unpack2(v);
    return f.x + f.y;
}

extern __shared__ float dsm[];

// smem layout (floats)
#define XS_FLOATS   (QT * 96 + 4)      // 12292
#define WPANEL      3072                // [k4][e][4] = 24*32*4

// ---------------------------------------------------------------------------
// Kernel 0: weight transpose prep (runs once, one block).
// ---------------------------------------------------------------------------
__global__ void __launch_bounds__(256) prep_kernel(
    const float* __restrict__ wqkv,
    const float* __restrict__ wproj)
{
    const int tid = threadIdx.x;
    for (int s = tid; s < 96 * 288; s += 256) {
        int k = s / 288, c = s - k * 288;
        int h = c / 96,  j = c - h * 96;
        int e = j / 3,   mat = j - e * 3;
        g_Wqkv[(h * 3 + mat) * 3072 + (k >> 2) * 128 + e * 4 + (k & 3)] = wqkv[s];
    }
    for (int s = tid; s < 96 * 96; s += 256) {
        int k = s / 96, c = s - k * 96;
        int j = c >> 5, e = c & 31;
        g_Wproj[j * 3072 + (k >> 2) * 128 + e * 4 + (k & 3)] = wproj[s];
    }
}

// ---------------------------------------------------------------------------
// Kernel 1: QKV GEMM + window scatter.
// grid (1568, 3), block 256, 2 blocks/SM.  Warp w: rows w*8.. in 2 passes.
// ---------------------------------------------------------------------------
__global__ void __launch_bounds__(256, 2) qkv_kernel(
    const float* __restrict__ x,
    const float* __restrict__ bqkv)
{
    float* xs = dsm;
    float* ws = dsm + XS_FLOATS;          // wq | wk | wv contiguous (3*3072)
    int*   rowdst = (int*)(ws + 3 * WPANEL);

    const int tile = blockIdx.x;
    const int h    = blockIdx.y;
    const int tid  = threadIdx.x;

    // stage x tile: pure float4 copy
    {
        const float4* xg = (const float4*)(x + (size_t)tile * (QT * 96));
        float4* xs4 = (float4*)xs;
        #pragma unroll
        for (int i = 0; i < (QT * 24) / 256; i++)
            xs4[tid + i * 256] = xg[tid + i * 256];
    }
    // stage weights: pure float4 copy
    {
        const float4* wg = (const float4*)(g_Wqkv + h * 3 * WPANEL);
        float4* wsm = (float4*)ws;
        #pragma unroll
        for (int i = 0; i < (3 * WPANEL) / 4 / 256; i++)
            wsm[tid + i * 256] = wg[tid + i * 256];
    }
    if (tid < QT) {
        int gr  = tile * QT + tid;
        int b   = gr / LDIM;
        int pix = gr - b * LDIM;
        int yy  = pix / IMG, xx = pix - yy * IMG;
        int win = (yy / WINSZ) * NWIN + (xx / WINSZ);
        int tok = (yy % WINSZ) * WINSZ + (xx % WINSZ);
        rowdst[tid] = (((b * HEADS + h) * (NWIN * NWIN) + win) * TOK + tok) * EDIM;
    }
    __syncthreads();

    const int e    = tid & 31;
    const int warp = tid >> 5;
    const float bq = bqkv[h * 96 + e * 3 + 0];
    const float bk = bqkv[h * 96 + e * 3 + 1];
    const float bv = bqkv[h * 96 + e * 3 + 2];
    const float* wqe = ws + e * 4;
    const float* wke = ws + WPANEL + e * 4;
    const float* wve = ws + 2 * WPANEL + e * 4;

    #pragma unroll 1
    for (int pass = 0; pass < 2; pass++) {
        const int r0 = pass * 64 + warp * NROW;
        const float* xb = xs + r0 * 96;

        u64 aq[NROW], ak[NROW], av[NROW];
        #pragma unroll
        for (int r = 0; r < NROW; r++) {
            aq[r] = pack2(bq, 0.f);
            ak[r] = pack2(bk, 0.f);
            av[r] = pack2(bv, 0.f);
        }

        #pragma unroll 2
        for (int k4 = 0; k4 < 24; k4++) {
            ulonglong2 wqv = *(const ulonglong2*)(wqe + k4 * 128);
            ulonglong2 wkv = *(const ulonglong2*)(wke + k4 * 128);
            ulonglong2 wvv = *(const ulonglong2*)(wve + k4 * 128);
            #pragma unroll
            for (int r = 0; r < NROW; r++) {
                ulonglong2 xr = *(const ulonglong2*)(xb + r * 96 + k4 * 4);
                aq[r] = fma2(xr.x, wqv.x, aq[r]);
                aq[r] = fma2(xr.y, wqv.y, aq[r]);
                ak[r] = fma2(xr.x, wkv.x, ak[r]);
                ak[r] = fma2(xr.y, wkv.y, ak[r]);
                av[r] = fma2(xr.x, wvv.x, av[r]);
                av[r] = fma2(xr.y, wvv.y, av[r]);
            }
        }

        #pragma unroll
        for (int r = 0; r < NROW; r++) {
            int d = rowdst[r0 + r] + e;
            g_Q[d] = hsum2(aq[r]);
            g_K[d] = hsum2(ak[r]);
            g_V[d] = hsum2(av[r]);
        }
    }
}

// ---------------------------------------------------------------------------
// Kernel 2: per-window attention, 2 windows per 128-thread block.
// R8 exact config: static smem, LB(128,4), single fused pass, single QK chain.
// ---------------------------------------------------------------------------
__global__ void __launch_bounds__(128, 4) attn_kernel(const float* __restrict__ rel_bias)
{
    __shared__ __align__(16) float Ks[2][TOK * EDIM];
    __shared__ __align__(16) float Vs[2][TOK * EDIM];
    __shared__ float Bs[TOK * TOK];

    const int tid  = threadIdx.x;
    const int half = tid >> 6;
    const int t    = tid & 63;
    const int widx = blockIdx.x * 2 + half;

    {
        const float4* kb = (const float4*)(g_K + (size_t)widx * (TOK * EDIM));
        const float4* vb = (const float4*)(g_V + (size_t)widx * (TOK * EDIM));
        float4* Ks4 = (float4*)Ks[half];
        float4* Vs4 = (float4*)Vs[half];
        for (int i = t; i < 392; i += 64) {
            Ks4[i] = kb[i];
            Vs4[i] = vb[i];
        }
    }
    for (int i = tid; i < TOK * TOK; i += 128) Bs[i] = rel_bias[i];
    __syncthreads();

    if (t < TOK) {
        const float* qb = g_Q + (size_t)widx * (TOK * EDIM) + t * EDIM;
        u64 qq[16];
        #pragma unroll
        for (int p = 0; p < 8; p++) {
            ulonglong2 qv = ((const ulonglong2*)qb)[p];
            qq[2 * p] = qv.x; qq[2 * p + 1] = qv.y;
        }

        const float scale = 0.17677669529663687f;  // 1/sqrt(32)
        const float* Kh = Ks[half];
        const float* Vh = Vs[half];
        const float* br = Bs + t * TOK;

        float sum = 0.f;
        u64 oo[16];
        #pragma unroll
        for (int p = 0; p < 16; p++) oo[p] = 0ull;

        #pragma unroll 7
        for (int j = 0; j < TOK; j++) {
            const ulonglong2* kr = (const ulonglong2*)(Kh + j * EDIM);
            u64 acc = 0ull;
            #pragma unroll
            for (int p = 0; p < 8; p++) {
                ulonglong2 kv = kr[p];
                acc = fma2(qq[2 * p], kv.x, acc);
                acc = fma2(qq[2 * p + 1], kv.y, acc);
            }
            float p = __expf(hsum2(acc) * scale + br[j]);
            sum += p;
            u64 pd = pack2(p, p);
            const ulonglong2* vr = (const ulonglong2*)(Vh + j * EDIM);
            #pragma unroll
            for (int u = 0; u < 8; u++) {
                ulonglong2 vv = vr[u];
                oo[2 * u]     = fma2(pd, vv.x, oo[2 * u]);
                oo[2 * u + 1] = fma2(pd, vv.y, oo[2 * u + 1]);
            }
        }
        float inv = 1.0f / sum;

        int b   = widx / (HEADS * NWIN * NWIN);
        int rem = widx - b * (HEADS * NWIN * NWIN);
        int h   = rem / (NWIN * NWIN);
        int win = rem - h * (NWIN * NWIN);
        int yy  = (win / NWIN) * WINSZ + t / WINSZ;
        int xx  = (win % NWIN) * WINSZ + t % WINSZ;
        float* dst = g_AO + ((size_t)b * LDIM + yy * IMG + xx) * CDIM + h * EDIM;
        #pragma unroll
        for (int u = 0; u < 8; u++) {
            float2 lo = unpack2(oo[2 * u]);
            float2 hi = unpack2(oo[2 * u + 1]);
            ((float4*)dst)[u] = make_float4(lo.x * inv, lo.y * inv,
                                            hi.x * inv, hi.y * inv);
        }
    }
}

// ---------------------------------------------------------------------------
// Kernel 3: output projection GEMM.  QT=128, 2 passes, pure-copy staging.
// Thread (e, warp): columns {e, e+32, e+64}.
// ---------------------------------------------------------------------------
__global__ void __launch_bounds__(256, 2) proj_kernel(
    const float* __restrict__ bproj,
    float* __restrict__ out)
{
    float* xs = dsm;
    float* ws = dsm + XS_FLOATS;   // w0 | w1 | w2 contiguous

    const int tile = blockIdx.x;
    const int tid  = threadIdx.x;

    {
        const float4* xg = (const float4*)(g_AO + (size_t)tile * (QT * 96));
        float4* xs4 = (float4*)xs;
        #pragma unroll
        for (int i = 0; i < (QT * 24) / 256; i++)
            xs4[tid + i * 256] = xg[tid + i * 256];
    }
    {
        const float4* wg = (const float4*)g_Wproj;
        float4* wsm = (float4*)ws;
        #pragma unroll
        for (int i = 0; i < (3 * WPANEL) / 4 / 256; i++)
            wsm[tid + i * 256] = wg[tid + i * 256];
    }
    __syncthreads();

    const int e    = tid & 31;
    const int warp = tid >> 5;
    const float b0 = bproj[e];
    const float b1 = bproj[32 + e];
    const float b2 = bproj[64 + e];
    const float* w0e = ws + e * 4;
    const float* w1e = ws + WPANEL + e * 4;
    const float* w2e = ws + 2 * WPANEL + e * 4;

    #pragma unroll 1
    for (int pass = 0; pass < 2; pass++) {
        const int r0 = pass * 64 + warp * NROW;
        const float* xb = xs + r0 * 96;

        u64 a0[NROW], a1[NROW], a2[NROW];
        #pragma unroll
        for (int r = 0; r < NROW; r++) {
            a0[r] = pack2(b0, 0.f);
            a1[r] = pack2(b1, 0.f);
            a2[r] = pack2(b2, 0.f);
        }

        #pragma unroll 2
        for (int k4 = 0; k4 < 24; k4++) {
            ulonglong2 w0v = *(const ulonglong2*)(w0e + k4 * 128);
            ulonglong2 w1v = *(const ulonglong2*)(w1e + k4 * 128);
            ulonglong2 w2v = *(const ulonglong2*)(w2e + k4 * 128);
            #pragma unroll
            for (int r = 0; r < NROW; r++) {
                ulonglong2 xr = *(const ulonglong2*)(xb + r * 96 + k4 * 4);
                a0[r] = fma2(xr.x, w0v.x, a0[r]);
                a0[r] = fma2(xr.y, w0v.y, a0[r]);
                a1[r] = fma2(xr.x, w1v.x, a1[r]);
                a1[r] = fma2(xr.y, w1v.y, a1[r]);
                a2[r] = fma2(xr.x, w2v.x, a2[r]);
                a2[r] = fma2(xr.y, w2v.y, a2[r]);
            }
        }

        float* ob = out + ((size_t)tile * QT + r0) * 96;
        #pragma unroll
        for (int r = 0; r < NROW; r++) {
            int o = r * 96;
            ob[o + e]      = hsum2(a0[r]);
            ob[o + 32 + e] = hsum2(a1[r]);
            ob[o + 64 + e] = hsum2(a2[r]);
        }
    }
}

// ---------------------------------------------------------------------------
extern "C" void kernel_launch(void* const* d_in, const int* in_sizes, int n_in,
                              void* d_out, int out_size)
{
    (void)in_sizes; (void)n_in; (void)out_size;
    const float* x        = (const float*)d_in[0];
    const float* w_qkv    = (const float*)d_in[1];
    const float* b_qkv    = (const float*)d_in[2];
    const float* w_proj   = (const float*)d_in[3];
    const float* b_proj   = (const float*)d_in[4];
    const float* rel_bias = (const float*)d_in[5];
    float* out = (float*)d_out;

    const int qkv_smem  = (XS_FLOATS + 3 * WPANEL + QT) * 4;
    const int proj_smem = (XS_FLOATS + 3 * WPANEL) * 4;
    cudaFuncSetAttribute(qkv_kernel,  cudaFuncAttributeMaxDynamicSharedMemorySize, qkv_smem);
    cudaFuncSetAttribute(proj_kernel, cudaFuncAttributeMaxDynamicSharedMemorySize, proj_smem);

    prep_kernel<<<1, 256>>>(w_qkv, w_proj);
    qkv_kernel<<<dim3(MROWS / QT, 3), 256, qkv_smem>>>(x, b_qkv);
    attn_kernel<<<WTOT / 2, 128>>>(rel_bias);
    proj_kernel<<<MROWS / QT, 256, proj_smem>>>(b_proj, out);
}

// round 16
// speedup vs baseline: 1.5896x; 1.2173x over previous
#include <cuda_runtime.h>
#include <cuda_bf16.h>
#include <cstdint>

// ---------------------------------------------------------------------------
// Swin window-MSA.  QKV GEMM on mma.sync.m16n8k16.bf16 (HMMA fallback path —
// tcgen05 PTX is rejected by this harness's sm_103 (non-'a') target) with
// hi/lo split-bf16 fp32 emulation.  attention + proj: measured-best FFMA2.
//   B=64, L=3136 (56x56), C=96, H=3, E=32, window 7x7 (49 tokens)
// ---------------------------------------------------------------------------

#define BATCH   64
#define IMG     56
#define WINSZ   7
#define NWIN    8
#define TOK     49
#define HEADS   3
#define CDIM    96
#define EDIM    32
#define LDIM    3136
#define MROWS   200704
#define WTOT    12288
#define QT      128
#define NROW    8
#define WSTRIDE 100352          // NWIN*NWIN*TOK*EDIM

typedef unsigned long long u64;

__device__ __align__(16) float g_Q[WTOT * TOK * EDIM];
__device__ __align__(16) float g_K[WTOT * TOK * EDIM];
__device__ __align__(16) float g_V[WTOT * TOK * EDIM];
__device__ __align__(16) float g_AO[MROWS * CDIM];
__device__ __align__(16) float g_Wproj[3 * 3072];
// qkv weights as bf16 hi/lo panels: [hl(2)][n=288][k=104], n = mat*96+h*32+e
__device__ __align__(16) unsigned char g_Bpack[2 * 288 * 104 * 2];
__device__ __align__(16) float g_brow[288];

// ---- packed f32x2 helpers (attn / proj) ----
__device__ __forceinline__ u64 pack2(float a, float b) {
    u64 r; asm("mov.b64 %0, {%1, %2};" : "=l"(r) : "f"(a), "f"(b)); return r;
}
__device__ __forceinline__ u64 fma2(u64 a, u64 b, u64 c) {
    u64 d; asm("fma.rn.f32x2 %0, %1, %2, %3;" : "=l"(d) : "l"(a), "l"(b), "l"(c)); return d;
}
__device__ __forceinline__ float2 unpack2(u64 v) {
    float2 f; asm("mov.b64 {%0, %1}, %2;" : "=f"(f.x), "=f"(f.y) : "l"(v)); return f;
}
__device__ __forceinline__ float hsum2(u64 v) { float2 f = unpack2(v); return f.x + f.y; }

// ---- mma.sync / ldmatrix helpers (baseline PTX, sm_80+) ----
__device__ __forceinline__ uint32_t smem_to_u32(const void* p) {
    uint32_t a;
    asm("{ .reg .u64 t; cvta.to.shared.u64 t, %1; cvt.u32.u64 %0, t; }" : "=r"(a) : "l"(p));
    return a;
}
__device__ __forceinline__ void ldsm_x4(uint32_t& r0, uint32_t& r1, uint32_t& r2,
                                        uint32_t& r3, uint32_t addr) {
    asm volatile("ldmatrix.sync.aligned.m8n8.x4.shared.b16 {%0,%1,%2,%3}, [%4];"
                 : "=r"(r0), "=r"(r1), "=r"(r2), "=r"(r3) : "r"(addr));
}
__device__ __forceinline__ void ldsm_x2(uint32_t& r0, uint32_t& r1, uint32_t addr) {
    asm volatile("ldmatrix.sync.aligned.m8n8.x2.shared.b16 {%0,%1}, [%2];"
                 : "=r"(r0), "=r"(r1) : "r"(addr));
}
__device__ __forceinline__ void mma16816(float* d,
                                         uint32_t a0, uint32_t a1, uint32_t a2, uint32_t a3,
                                         uint32_t b0, uint32_t b1) {
    asm volatile("mma.sync.aligned.m16n8k16.row.col.f32.bf16.bf16.f32 "
                 "{%0,%1,%2,%3}, {%4,%5,%6,%7}, {%8,%9}, {%0,%1,%2,%3};"
                 : "+f"(d[0]), "+f"(d[1]), "+f"(d[2]), "+f"(d[3])
                 : "r"(a0), "r"(a1), "r"(a2), "r"(a3), "r"(b0), "r"(b1));
}
__device__ __forceinline__ void bsplit(float v, unsigned short& h, unsigned short& l) {
    __nv_bfloat16 hb = __float2bfloat16(v);
    float hf = __bfloat162float(hb);
    __nv_bfloat16 lb = __float2bfloat16(v - hf);
    h = *(unsigned short*)&hb;
    l = *(unsigned short*)&lb;
}

extern __shared__ float dsm[];

#define XS_FLOATS   (QT * 96 + 4)
#define WPANEL      3072

// smem byte offsets for qkv_mma (stride 104 bf16 = 208 B per row)
#define SM_AH   0                      // 128*208 = 26624
#define SM_AL   26624
#define SM_BH   53248                  // 288*208 = 59904
#define SM_BL   113152
#define SM_BROW 173056                 // 288 floats
#define SM_RD   174208                 // 128 ints
#define SM_TOT  174720

// ---------------------------------------------------------------------------
// Kernel 0: prep — proj weights [k4][e][4]; qkv W bf16 hi/lo panels; bias.
// ---------------------------------------------------------------------------
__global__ void __launch_bounds__(256) prep_kernel(
    const float* __restrict__ wqkv,
    const float* __restrict__ bqkv,
    const float* __restrict__ wproj)
{
    const int tid = threadIdx.x;
    for (int s = tid; s < 96 * 96; s += 256) {
        int k = s / 96, c = s - k * 96;
        int j = c >> 5, e = c & 31;
        g_Wproj[j * 3072 + (k >> 2) * 128 + e * 4 + (k & 3)] = wproj[s];
    }
    unsigned short* bp = (unsigned short*)g_Bpack;
    for (int s = tid; s < 288 * 104; s += 256) {
        int n = s / 104, k = s - n * 104;
        int mat = n / 96, rem = n - mat * 96;
        int h = rem >> 5, e = rem & 31;
        float v = (k < 96) ? wqkv[k * 288 + h * 96 + e * 3 + mat] : 0.f;
        unsigned short hs, ls;
        bsplit(v, hs, ls);
        bp[n * 104 + k]              = hs;
        bp[288 * 104 + n * 104 + k]  = ls;
    }
    for (int n = tid; n < 288; n += 256) {
        int mat = n / 96, rem = n - mat * 96;
        int h = rem >> 5, e = rem & 31;
        g_brow[n] = bqkv[h * 96 + e * 3 + mat];
    }
}

// ---------------------------------------------------------------------------
// QKV epilogue: bias add + window scatter, NB = warp's n-base (0 or 144).
// ---------------------------------------------------------------------------
template <int NB>
__device__ __forceinline__ void qkv_epilogue(
    float (*d)[18][4], const int* rowdst, const float* brow,
    int m0, int gr, int gc2)
{
    #pragma unroll
    for (int mt = 0; mt < 2; mt++) {
        int r   = m0 + mt * 16 + gr;
        int rd0 = rowdst[r];
        int rd1 = rowdst[r + 8];
        #pragma unroll
        for (int nt = 0; nt < 18; nt++) {
            const int n0  = NB + nt * 8;
            const int mat = n0 / 96;
            const int hh  = (n0 % 96) / 32;
            const int e0  = (n0 % 96) % 32;
            float* base = (mat == 0) ? g_Q : (mat == 1) ? g_K : g_V;
            float b0 = brow[n0 + gc2];
            float b1 = brow[n0 + gc2 + 1];
            int off = hh * WSTRIDE + e0 + gc2;
            *(float2*)(base + rd0 + off) = make_float2(d[mt][nt][0] + b0, d[mt][nt][1] + b1);
            *(float2*)(base + rd1 + off) = make_float2(d[mt][nt][2] + b0, d[mt][nt][3] + b1);
        }
    }
}

// ---------------------------------------------------------------------------
// Kernel 1: QKV GEMM on mma.sync.  grid 1568, 256 threads (8 warps).
// Warp (w&3) owns 32 rows; (w>>2) owns 144 cols.  3 variants x 6 k-steps.
// ---------------------------------------------------------------------------
__global__ void __launch_bounds__(256) qkv_mma_kernel(const float* __restrict__ x)
{
    char* smc = (char*)dsm;
    const uint32_t smem_base = smem_to_u32(smc);
    const int tid  = threadIdx.x;
    const int tile = blockIdx.x;

    // stage A: fp32 -> bf16 hi/lo panels (stride 104 bf16)
    {
        const float4* xg = (const float4*)(x + (size_t)tile * (128 * 96));
        #pragma unroll
        for (int it = 0; it < 12; it++) {
            int i = tid + it * 256;                 // 3072 float4 total
            float4 v = xg[i];
            int row = i / 24, kq = i - row * 24;    // kq in float4 units
            ushort4 hi, lo;
            bsplit(v.x, hi.x, lo.x);
            bsplit(v.y, hi.y, lo.y);
            bsplit(v.z, hi.z, lo.z);
            bsplit(v.w, hi.w, lo.w);
            *(ushort4*)(smc + SM_AH + row * 208 + kq * 8) = hi;
            *(ushort4*)(smc + SM_AL + row * 208 + kq * 8) = lo;
        }
    }
    // stage B: pure 16B copies of pre-split panels (hi then lo, contiguous)
    {
        const uint4* sB = (const uint4*)g_Bpack;
        uint4* dB = (uint4*)(smc + SM_BH);
        for (int i = tid; i < 7488; i += 256) dB[i] = sB[i];
    }
    float* brow = (float*)(smc + SM_BROW);
    for (int i = tid; i < 288; i += 256) brow[i] = g_brow[i];
    int* rowdst = (int*)(smc + SM_RD);
    if (tid < 128) {
        int gr  = tile * 128 + tid;
        int b   = gr / LDIM;
        int pix = gr - b * LDIM;
        int yy  = pix / IMG, xx = pix - yy * IMG;
        int win = (yy / WINSZ) * NWIN + (xx / WINSZ);
        int tok = (yy % WINSZ) * WINSZ + (xx % WINSZ);
        rowdst[tid] = ((b * (HEADS * NWIN * NWIN) + win) * TOK + tok) * EDIM;  // h=0 base
    }
    __syncthreads();

    const int l  = tid & 31;
    const int w  = tid >> 5;
    const int m0 = (w & 3) * 32;
    const int NBr = (w >> 2) * 144;

    // lane geometry for ldmatrix
    const int arow   = (l & 7) + ((l >> 3) & 1) * 8;   // A: row within 16-row tile
    const int acol16 = ((l >> 4) & 1) * 16;            // A: k byte offset (+8 bf16)
    const int brw    = (l & 7);                        // B: n row within 8
    const int bcol16 = ((l >> 3) & 1) * 16;            // B: k byte offset

    float d[2][18][4];
    #pragma unroll
    for (int mt = 0; mt < 2; mt++)
        #pragma unroll
        for (int nt = 0; nt < 18; nt++)
            #pragma unroll
            for (int q = 0; q < 4; q++) d[mt][nt][q] = 0.f;

    #pragma unroll 1
    for (int v = 0; v < 3; v++) {
        const uint32_t Ap = smem_base + ((v == 2) ? SM_AL : SM_AH);
        const uint32_t Bp = smem_base + ((v == 1) ? SM_BL : SM_BH);
        const uint32_t aAddr = Ap + (uint32_t)((m0 + arow) * 208 + acol16);
        const uint32_t bAddr = Bp + (uint32_t)((NBr + brw) * 208 + bcol16);
        #pragma unroll 1
        for (int kk = 0; kk < 6; kk++) {
            uint32_t a00, a01, a02, a03, a10, a11, a12, a13;
            ldsm_x4(a00, a01, a02, a03, aAddr + kk * 32);
            ldsm_x4(a10, a11, a12, a13, aAddr + 16 * 208 + kk * 32);
            #pragma unroll
            for (int nt = 0; nt < 18; nt++) {
                uint32_t b0, b1;
                ldsm_x2(b0, b1, bAddr + nt * (8 * 208) + kk * 32);
                mma16816(d[0][nt], a00, a01, a02, a03, b0, b1);
                mma16816(d[1][nt], a10, a11, a12, a13, b0, b1);
            }
        }
    }

    const int gr  = l >> 2;
    const int gc2 = (l & 3) * 2;
    if (w < 4) qkv_epilogue<0>(d, rowdst, brow, m0, gr, gc2);
    else       qkv_epilogue<144>(d, rowdst, brow, m0, gr, gc2);
}

// ---------------------------------------------------------------------------
// Kernel 2: per-window attention (measured-best config, unchanged).
// ---------------------------------------------------------------------------
__global__ void __launch_bounds__(128, 4) attn_kernel(const float* __restrict__ rel_bias)
{
    __shared__ __align__(16) float Ks[2][TOK * EDIM];
    __shared__ __align__(16) float Vs[2][TOK * EDIM];
    __shared__ float Bs[TOK * TOK];

    const int tid  = threadIdx.x;
    const int half = tid >> 6;
    const int t    = tid & 63;
    const int widx = blockIdx.x * 2 + half;

    {
        const float4* kb = (const float4*)(g_K + (size_t)widx * (TOK * EDIM));
        const float4* vb = (const float4*)(g_V + (size_t)widx * (TOK * EDIM));
        float4* Ks4 = (float4*)Ks[half];
        float4* Vs4 = (float4*)Vs[half];
        for (int i = t; i < 392; i += 64) { Ks4[i] = kb[i]; Vs4[i] = vb[i]; }
    }
    for (int i = tid; i < TOK * TOK; i += 128) Bs[i] = rel_bias[i];
    __syncthreads();

    if (t < TOK) {
        const float* qb = g_Q + (size_t)widx * (TOK * EDIM) + t * EDIM;
        u64 qq[16];
        #pragma unroll
        for (int p = 0; p < 8; p++) {
            ulonglong2 qv = ((const ulonglong2*)qb)[p];
            qq[2 * p] = qv.x; qq[2 * p + 1] = qv.y;
        }
        const float scale = 0.17677669529663687f;
        const float* Kh = Ks[half];
        const float* Vh = Vs[half];
        const float* br = Bs + t * TOK;

        float sum = 0.f;
        u64 oo[16];
        #pragma unroll
        for (int p = 0; p < 16; p++) oo[p] = 0ull;

        #pragma unroll 7
        for (int j = 0; j < TOK; j++) {
            const ulonglong2* kr = (const ulonglong2*)(Kh + j * EDIM);
            u64 acc = 0ull;
            #pragma unroll
            for (int p = 0; p < 8; p++) {
                ulonglong2 kv = kr[p];
                acc = fma2(qq[2 * p], kv.x, acc);
                acc = fma2(qq[2 * p + 1], kv.y, acc);
            }
            float p = __expf(hsum2(acc) * scale + br[j]);
            sum += p;
            u64 pd = pack2(p, p);
            const ulonglong2* vr = (const ulonglong2*)(Vh + j * EDIM);
            #pragma unroll
            for (int u = 0; u < 8; u++) {
                ulonglong2 vv = vr[u];
                oo[2 * u]     = fma2(pd, vv.x, oo[2 * u]);
                oo[2 * u + 1] = fma2(pd, vv.y, oo[2 * u + 1]);
            }
        }
        float inv = 1.0f / sum;

        int b   = widx / (HEADS * NWIN * NWIN);
        int rem = widx - b * (HEADS * NWIN * NWIN);
        int h   = rem / (NWIN * NWIN);
        int win = rem - h * (NWIN * NWIN);
        int yy  = (win / NWIN) * WINSZ + t / WINSZ;
        int xx  = (win % NWIN) * WINSZ + t % WINSZ;
        float* dst = g_AO + ((size_t)b * LDIM + yy * IMG + xx) * CDIM + h * EDIM;
        #pragma unroll
        for (int u = 0; u < 8; u++) {
            float2 lo = unpack2(oo[2 * u]);
            float2 hi = unpack2(oo[2 * u + 1]);
            ((float4*)dst)[u] = make_float4(lo.x * inv, lo.y * inv, hi.x * inv, hi.y * inv);
        }
    }
}

// ---------------------------------------------------------------------------
// Kernel 3: output projection (measured-best config, unchanged).
// ---------------------------------------------------------------------------
__global__ void __launch_bounds__(256, 2) proj_kernel(
    const float* __restrict__ bproj,
    float* __restrict__ out)
{
    float* xs = dsm;
    float* ws = dsm + XS_FLOATS;

    const int tile = blockIdx.x;
    const int tid  = threadIdx.x;

    {
        const float4* xg = (const float4*)(g_AO + (size_t)tile * (QT * 96));
        float4* xs4 = (float4*)xs;
        #pragma unroll
        for (int i = 0; i < (QT * 24) / 256; i++)
            xs4[tid + i * 256] = xg[tid + i * 256];
    }
    {
        const float4* wg = (const float4*)g_Wproj;
        float4* wsm = (float4*)ws;
        #pragma unroll
        for (int i = 0; i < (3 * WPANEL) / 4 / 256; i++)
            wsm[tid + i * 256] = wg[tid + i * 256];
    }
    __syncthreads();

    const int e    = tid & 31;
    const int warp = tid >> 5;
    const float b0 = bproj[e];
    const float b1 = bproj[32 + e];
    const float b2 = bproj[64 + e];
    const float* w0e = ws + e * 4;
    const float* w1e = ws + WPANEL + e * 4;
    const float* w2e = ws + 2 * WPANEL + e * 4;

    #pragma unroll 1
    for (int pass = 0; pass < 2; pass++) {
        const int r0 = pass * 64 + warp * NROW;
        const float* xb = xs + r0 * 96;

        u64 a0[NROW], a1[NROW], a2[NROW];
        #pragma unroll
        for (int r = 0; r < NROW; r++) {
            a0[r] = pack2(b0, 0.f);
            a1[r] = pack2(b1, 0.f);
            a2[r] = pack2(b2, 0.f);
        }

        #pragma unroll 2
        for (int k4 = 0; k4 < 24; k4++) {
            ulonglong2 w0v = *(const ulonglong2*)(w0e + k4 * 128);
            ulonglong2 w1v = *(const ulonglong2*)(w1e + k4 * 128);
            ulonglong2 w2v = *(const ulonglong2*)(w2e + k4 * 128);
            #pragma unroll
            for (int r = 0; r < NROW; r++) {
                ulonglong2 xr = *(const ulonglong2*)(xb + r * 96 + k4 * 4);
                a0[r] = fma2(xr.x, w0v.x, a0[r]);
                a0[r] = fma2(xr.y, w0v.y, a0[r]);
                a1[r] = fma2(xr.x, w1v.x, a1[r]);
                a1[r] = fma2(xr.y, w1v.y, a1[r]);
                a2[r] = fma2(xr.x, w2v.x, a2[r]);
                a2[r] = fma2(xr.y, w2v.y, a2[r]);
            }
        }

        float* ob = out + ((size_t)tile * QT + r0) * 96;
        #pragma unroll
        for (int r = 0; r < NROW; r++) {
            int o = r * 96;
            ob[o + e]      = hsum2(a0[r]);
            ob[o + 32 + e] = hsum2(a1[r]);
            ob[o + 64 + e] = hsum2(a2[r]);
        }
    }
}

// ---------------------------------------------------------------------------
extern "C" void kernel_launch(void* const* d_in, const int* in_sizes, int n_in,
                              void* d_out, int out_size)
{
    (void)in_sizes; (void)n_in; (void)out_size;
    const float* x        = (const float*)d_in[0];
    const float* w_qkv    = (const float*)d_in[1];
    const float* b_qkv    = (const float*)d_in[2];
    const float* w_proj   = (const float*)d_in[3];
    const float* b_proj   = (const float*)d_in[4];
    const float* rel_bias = (const float*)d_in[5];
    float* out = (float*)d_out;

    const int proj_smem = (XS_FLOATS + 3 * WPANEL) * 4;
    cudaFuncSetAttribute(proj_kernel, cudaFuncAttributeMaxDynamicSharedMemorySize, proj_smem);
    cudaFuncSetAttribute(qkv_mma_kernel, cudaFuncAttributeMaxDynamicSharedMemorySize, SM_TOT);

    prep_kernel<<<1, 256>>>(w_qkv, b_qkv, w_proj);
    qkv_mma_kernel<<<MROWS / QT, 256, SM_TOT>>>(x);
    attn_kernel<<<WTOT / 2, 128>>>(rel_bias);
    proj_kernel<<<MROWS / QT, 256, proj_smem>>>(b_proj, out);
}

// round 17
// speedup vs baseline: 1.7229x; 1.0839x over previous
#include <cuda_runtime.h>
#include <cuda_bf16.h>
#include <cstdint>

// ---------------------------------------------------------------------------
// Swin window-MSA.  Both GEMMs on mma.sync.m16n8k16.bf16 (HMMA path; tcgen05
// PTX rejected by this harness's sm_103 non-'a' target) with hi/lo split-bf16
// fp32 emulation.  Attention: measured-best FFMA2 kernel.
//   B=64, L=3136 (56x56), C=96, H=3, E=32, window 7x7 (49 tokens)
// ---------------------------------------------------------------------------

#define BATCH   64
#define IMG     56
#define WINSZ   7
#define NWIN    8
#define TOK     49
#define HEADS   3
#define CDIM    96
#define EDIM    32
#define LDIM    3136
#define MROWS   200704
#define WTOT    12288
#define QT      128
#define WSTRIDE 100352          // NWIN*NWIN*TOK*EDIM

typedef unsigned long long u64;

__device__ __align__(16) float g_Q[WTOT * TOK * EDIM];
__device__ __align__(16) float g_K[WTOT * TOK * EDIM];
__device__ __align__(16) float g_V[WTOT * TOK * EDIM];
__device__ __align__(16) float g_AO[MROWS * CDIM];
// qkv weights as bf16 hi/lo panels: [hl(2)][n=288][k=104], n = mat*96+h*32+e
__device__ __align__(16) unsigned char g_Bpack[2 * 288 * 104 * 2];
__device__ __align__(16) float g_brow[288];
// proj weights as bf16 hi/lo panels: [hl(2)][n=96][k=104], n = output col
__device__ __align__(16) unsigned char g_BpackP[2 * 96 * 104 * 2];

// ---- packed f32x2 helpers (attn) ----
__device__ __forceinline__ u64 pack2(float a, float b) {
    u64 r; asm("mov.b64 %0, {%1, %2};" : "=l"(r) : "f"(a), "f"(b)); return r;
}
__device__ __forceinline__ u64 fma2(u64 a, u64 b, u64 c) {
    u64 d; asm("fma.rn.f32x2 %0, %1, %2, %3;" : "=l"(d) : "l"(a), "l"(b), "l"(c)); return d;
}
__device__ __forceinline__ float2 unpack2(u64 v) {
    float2 f; asm("mov.b64 {%0, %1}, %2;" : "=f"(f.x), "=f"(f.y) : "l"(v)); return f;
}
__device__ __forceinline__ float hsum2(u64 v) { float2 f = unpack2(v); return f.x + f.y; }

// ---- mma.sync / ldmatrix helpers (baseline PTX, sm_80+) ----
__device__ __forceinline__ uint32_t smem_to_u32(const void* p) {
    uint32_t a;
    asm("{ .reg .u64 t; cvta.to.shared.u64 t, %1; cvt.u32.u64 %0, t; }" : "=r"(a) : "l"(p));
    return a;
}
__device__ __forceinline__ void ldsm_x4(uint32_t& r0, uint32_t& r1, uint32_t& r2,
                                        uint32_t& r3, uint32_t addr) {
    asm volatile("ldmatrix.sync.aligned.m8n8.x4.shared.b16 {%0,%1,%2,%3}, [%4];"
                 : "=r"(r0), "=r"(r1), "=r"(r2), "=r"(r3) : "r"(addr));
}
__device__ __forceinline__ void ldsm_x2(uint32_t& r0, uint32_t& r1, uint32_t addr) {
    asm volatile("ldmatrix.sync.aligned.m8n8.x2.shared.b16 {%0,%1}, [%2];"
                 : "=r"(r0), "=r"(r1) : "r"(addr));
}
__device__ __forceinline__ void mma16816(float* d,
                                         uint32_t a0, uint32_t a1, uint32_t a2, uint32_t a3,
                                         uint32_t b0, uint32_t b1) {
    asm volatile("mma.sync.aligned.m16n8k16.row.col.f32.bf16.bf16.f32 "
                 "{%0,%1,%2,%3}, {%4,%5,%6,%7}, {%8,%9}, {%0,%1,%2,%3};"
                 : "+f"(d[0]), "+f"(d[1]), "+f"(d[2]), "+f"(d[3])
                 : "r"(a0), "r"(a1), "r"(a2), "r"(a3), "r"(b0), "r"(b1));
}
__device__ __forceinline__ void bsplit(float v, unsigned short& h, unsigned short& l) {
    __nv_bfloat16 hb = __float2bfloat16(v);
    float hf = __bfloat162float(hb);
    __nv_bfloat16 lb = __float2bfloat16(v - hf);
    h = *(unsigned short*)&hb;
    l = *(unsigned short*)&lb;
}

extern __shared__ float dsm[];

// qkv_mma smem byte offsets (stride 104 bf16 = 208 B per row)
#define SM_AH   0                      // 128*208 = 26624
#define SM_AL   26624
#define SM_BH   53248                  // 288*208 = 59904
#define SM_BL   113152
#define SM_BROW 173056                 // 288 floats
#define SM_RD   174208                 // 128 ints
#define SM_TOT  174720

// proj_mma smem byte offsets
#define PM_AH   0                      // 128*208 = 26624
#define PM_AL   26624
#define PM_BH   53248                  // 96*208 = 19968
#define PM_BL   73216
#define PM_BROW 93184                  // 96 floats
#define PM_TOT  93568

// ---------------------------------------------------------------------------
// Kernel 0: prep — qkv + proj weights to bf16 hi/lo panels; qkv bias reorder.
// ---------------------------------------------------------------------------
__global__ void __launch_bounds__(256) prep_kernel(
    const float* __restrict__ wqkv,
    const float* __restrict__ bqkv,
    const float* __restrict__ wproj)
{
    const int tid = threadIdx.x;
    unsigned short* bp = (unsigned short*)g_Bpack;
    for (int s = tid; s < 288 * 104; s += 256) {
        int n = s / 104, k = s - n * 104;
        int mat = n / 96, rem = n - mat * 96;
        int h = rem >> 5, e = rem & 31;
        float v = (k < 96) ? wqkv[k * 288 + h * 96 + e * 3 + mat] : 0.f;
        unsigned short hs, ls;
        bsplit(v, hs, ls);
        bp[n * 104 + k]             = hs;
        bp[288 * 104 + n * 104 + k] = ls;
    }
    unsigned short* pp = (unsigned short*)g_BpackP;
    for (int s = tid; s < 96 * 104; s += 256) {
        int n = s / 104, k = s - n * 104;
        float v = (k < 96) ? wproj[k * 96 + n] : 0.f;
        unsigned short hs, ls;
        bsplit(v, hs, ls);
        pp[n * 104 + k]            = hs;
        pp[96 * 104 + n * 104 + k] = ls;
    }
    for (int n = tid; n < 288; n += 256) {
        int mat = n / 96, rem = n - mat * 96;
        int h = rem >> 5, e = rem & 31;
        g_brow[n] = bqkv[h * 96 + e * 3 + mat];
    }
}

// ---------------------------------------------------------------------------
// QKV epilogue: bias add + window scatter, NB = warp's n-base (0 or 144).
// ---------------------------------------------------------------------------
template <int NB>
__device__ __forceinline__ void qkv_epilogue(
    float (*d)[18][4], const int* rowdst, const float* brow,
    int m0, int gr, int gc2)
{
    #pragma unroll
    for (int mt = 0; mt < 2; mt++) {
        int r   = m0 + mt * 16 + gr;
        int rd0 = rowdst[r];
        int rd1 = rowdst[r + 8];
        #pragma unroll
        for (int nt = 0; nt < 18; nt++) {
            const int n0  = NB + nt * 8;
            const int mat = n0 / 96;
            const int hh  = (n0 % 96) / 32;
            const int e0  = (n0 % 96) % 32;
            float* base = (mat == 0) ? g_Q : (mat == 1) ? g_K : g_V;
            float b0 = brow[n0 + gc2];
            float b1 = brow[n0 + gc2 + 1];
            int off = hh * WSTRIDE + e0 + gc2;
            *(float2*)(base + rd0 + off) = make_float2(d[mt][nt][0] + b0, d[mt][nt][1] + b1);
            *(float2*)(base + rd1 + off) = make_float2(d[mt][nt][2] + b0, d[mt][nt][3] + b1);
        }
    }
}

// ---------------------------------------------------------------------------
// Kernel 1: QKV GEMM on mma.sync (passing config from R15, unchanged).
// ---------------------------------------------------------------------------
__global__ void __launch_bounds__(256) qkv_mma_kernel(const float* __restrict__ x)
{
    char* smc = (char*)dsm;
    const uint32_t smem_base = smem_to_u32(smc);
    const int tid  = threadIdx.x;
    const int tile = blockIdx.x;

    {
        const float4* xg = (const float4*)(x + (size_t)tile * (128 * 96));
        #pragma unroll
        for (int it = 0; it < 12; it++) {
            int i = tid + it * 256;
            float4 v = xg[i];
            int row = i / 24, kq = i - row * 24;
            ushort4 hi, lo;
            bsplit(v.x, hi.x, lo.x);
            bsplit(v.y, hi.y, lo.y);
            bsplit(v.z, hi.z, lo.z);
            bsplit(v.w, hi.w, lo.w);
            *(ushort4*)(smc + SM_AH + row * 208 + kq * 8) = hi;
            *(ushort4*)(smc + SM_AL + row * 208 + kq * 8) = lo;
        }
    }
    {
        const uint4* sB = (const uint4*)g_Bpack;
        uint4* dB = (uint4*)(smc + SM_BH);
        for (int i = tid; i < 7488; i += 256) dB[i] = sB[i];
    }
    float* brow = (float*)(smc + SM_BROW);
    for (int i = tid; i < 288; i += 256) brow[i] = g_brow[i];
    int* rowdst = (int*)(smc + SM_RD);
    if (tid < 128) {
        int gr  = tile * 128 + tid;
        int b   = gr / LDIM;
        int pix = gr - b * LDIM;
        int yy  = pix / IMG, xx = pix - yy * IMG;
        int win = (yy / WINSZ) * NWIN + (xx / WINSZ);
        int tok = (yy % WINSZ) * WINSZ + (xx % WINSZ);
        rowdst[tid] = ((b * (HEADS * NWIN * NWIN) + win) * TOK + tok) * EDIM;
    }
    __syncthreads();

    const int l  = tid & 31;
    const int w  = tid >> 5;
    const int m0 = (w & 3) * 32;
    const int NBr = (w >> 2) * 144;

    const int arow   = (l & 7) + ((l >> 3) & 1) * 8;
    const int acol16 = ((l >> 4) & 1) * 16;
    const int brw    = (l & 7);
    const int bcol16 = ((l >> 3) & 1) * 16;

    float d[2][18][4];
    #pragma unroll
    for (int mt = 0; mt < 2; mt++)
        #pragma unroll
        for (int nt = 0; nt < 18; nt++)
            #pragma unroll
            for (int q = 0; q < 4; q++) d[mt][nt][q] = 0.f;

    #pragma unroll 1
    for (int v = 0; v < 3; v++) {
        const uint32_t Ap = smem_base + ((v == 2) ? SM_AL : SM_AH);
        const uint32_t Bp = smem_base + ((v == 1) ? SM_BL : SM_BH);
        const uint32_t aAddr = Ap + (uint32_t)((m0 + arow) * 208 + acol16);
        const uint32_t bAddr = Bp + (uint32_t)((NBr + brw) * 208 + bcol16);
        #pragma unroll 1
        for (int kk = 0; kk < 6; kk++) {
            uint32_t a00, a01, a02, a03, a10, a11, a12, a13;
            ldsm_x4(a00, a01, a02, a03, aAddr + kk * 32);
            ldsm_x4(a10, a11, a12, a13, aAddr + 16 * 208 + kk * 32);
            #pragma unroll
            for (int nt = 0; nt < 18; nt++) {
                uint32_t b0, b1;
                ldsm_x2(b0, b1, bAddr + nt * (8 * 208) + kk * 32);
                mma16816(d[0][nt], a00, a01, a02, a03, b0, b1);
                mma16816(d[1][nt], a10, a11, a12, a13, b0, b1);
            }
        }
    }

    const int gr  = l >> 2;
    const int gc2 = (l & 3) * 2;
    if (w < 4) qkv_epilogue<0>(d, rowdst, brow, m0, gr, gc2);
    else       qkv_epilogue<144>(d, rowdst, brow, m0, gr, gc2);
}

// ---------------------------------------------------------------------------
// Kernel 2: per-window attention (measured-best config, unchanged).
// ---------------------------------------------------------------------------
__global__ void __launch_bounds__(128, 4) attn_kernel(const float* __restrict__ rel_bias)
{
    __shared__ __align__(16) float Ks[2][TOK * EDIM];
    __shared__ __align__(16) float Vs[2][TOK * EDIM];
    __shared__ float Bs[TOK * TOK];

    const int tid  = threadIdx.x;
    const int half = tid >> 6;
    const int t    = tid & 63;
    const int widx = blockIdx.x * 2 + half;

    {
        const float4* kb = (const float4*)(g_K + (size_t)widx * (TOK * EDIM));
        const float4* vb = (const float4*)(g_V + (size_t)widx * (TOK * EDIM));
        float4* Ks4 = (float4*)Ks[half];
        float4* Vs4 = (float4*)Vs[half];
        for (int i = t; i < 392; i += 64) { Ks4[i] = kb[i]; Vs4[i] = vb[i]; }
    }
    for (int i = tid; i < TOK * TOK; i += 128) Bs[i] = rel_bias[i];
    __syncthreads();

    if (t < TOK) {
        const float* qb = g_Q + (size_t)widx * (TOK * EDIM) + t * EDIM;
        u64 qq[16];
        #pragma unroll
        for (int p = 0; p < 8; p++) {
            ulonglong2 qv = ((const ulonglong2*)qb)[p];
            qq[2 * p] = qv.x; qq[2 * p + 1] = qv.y;
        }
        const float scale = 0.17677669529663687f;
        const float* Kh = Ks[half];
        const float* Vh = Vs[half];
        const float* br = Bs + t * TOK;

        float sum = 0.f;
        u64 oo[16];
        #pragma unroll
        for (int p = 0; p < 16; p++) oo[p] = 0ull;

        #pragma unroll 7
        for (int j = 0; j < TOK; j++) {
            const ulonglong2* kr = (const ulonglong2*)(Kh + j * EDIM);
            u64 acc = 0ull;
            #pragma unroll
            for (int p = 0; p < 8; p++) {
                ulonglong2 kv = kr[p];
                acc = fma2(qq[2 * p], kv.x, acc);
                acc = fma2(qq[2 * p + 1], kv.y, acc);
            }
            float p = __expf(hsum2(acc) * scale + br[j]);
            sum += p;
            u64 pd = pack2(p, p);
            const ulonglong2* vr = (const ulonglong2*)(Vh + j * EDIM);
            #pragma unroll
            for (int u = 0; u < 8; u++) {
                ulonglong2 vv = vr[u];
                oo[2 * u]     = fma2(pd, vv.x, oo[2 * u]);
                oo[2 * u + 1] = fma2(pd, vv.y, oo[2 * u + 1]);
            }
        }
        float inv = 1.0f / sum;

        int b   = widx / (HEADS * NWIN * NWIN);
        int rem = widx - b * (HEADS * NWIN * NWIN);
        int h   = rem / (NWIN * NWIN);
        int win = rem - h * (NWIN * NWIN);
        int yy  = (win / NWIN) * WINSZ + t / WINSZ;
        int xx  = (win % NWIN) * WINSZ + t % WINSZ;
        float* dst = g_AO + ((size_t)b * LDIM + yy * IMG + xx) * CDIM + h * EDIM;
        #pragma unroll
        for (int u = 0; u < 8; u++) {
            float2 lo = unpack2(oo[2 * u]);
            float2 hi = unpack2(oo[2 * u + 1]);
            ((float4*)dst)[u] = make_float4(lo.x * inv, lo.y * inv, hi.x * inv, hi.y * inv);
        }
    }
}

// ---------------------------------------------------------------------------
// Kernel 3: output projection on mma.sync (same template as qkv, N=96,
// dense row-major epilogue).  grid 1568, 256 threads (8 warps).
// Warp (w&3) owns 32 rows; (w>>2) owns 48 cols (6 n-tiles of 8).
// ---------------------------------------------------------------------------
__global__ void __launch_bounds__(256, 2) proj_mma_kernel(
    const float* __restrict__ bproj,
    float* __restrict__ out)
{
    char* smc = (char*)dsm;
    const uint32_t smem_base = smem_to_u32(smc);
    const int tid  = threadIdx.x;
    const int tile = blockIdx.x;

    // stage A: g_AO fp32 -> bf16 hi/lo panels
    {
        const float4* xg = (const float4*)(g_AO + (size_t)tile * (128 * 96));
        #pragma unroll
        for (int it = 0; it < 12; it++) {
            int i = tid + it * 256;
            float4 v = xg[i];
            int row = i / 24, kq = i - row * 24;
            ushort4 hi, lo;
            bsplit(v.x, hi.x, lo.x);
            bsplit(v.y, hi.y, lo.y);
            bsplit(v.z, hi.z, lo.z);
            bsplit(v.w, hi.w, lo.w);
            *(ushort4*)(smc + PM_AH + row * 208 + kq * 8) = hi;
            *(ushort4*)(smc + PM_AL + row * 208 + kq * 8) = lo;
        }
    }
    // stage B: pure 16B copies (hi + lo contiguous: 39936 B = 2496 uint4)
    {
        const uint4* sB = (const uint4*)g_BpackP;
        uint4* dB = (uint4*)(smc + PM_BH);
        for (int i = tid; i < 2496; i += 256) dB[i] = sB[i];
    }
    float* brow = (float*)(smc + PM_BROW);
    if (tid < 96) brow[tid] = bproj[tid];
    __syncthreads();

    const int l  = tid & 31;
    const int w  = tid >> 5;
    const int m0 = (w & 3) * 32;
    const int NBr = (w >> 2) * 48;

    const int arow   = (l & 7) + ((l >> 3) & 1) * 8;
    const int acol16 = ((l >> 4) & 1) * 16;
    const int brw    = (l & 7);
    const int bcol16 = ((l >> 3) & 1) * 16;

    float d[2][6][4];
    #pragma unroll
    for (int mt = 0; mt < 2; mt++)
        #pragma unroll
        for (int nt = 0; nt < 6; nt++)
            #pragma unroll
            for (int q = 0; q < 4; q++) d[mt][nt][q] = 0.f;

    #pragma unroll 1
    for (int v = 0; v < 3; v++) {
        const uint32_t Ap = smem_base + ((v == 2) ? PM_AL : PM_AH);
        const uint32_t Bp = smem_base + ((v == 1) ? PM_BL : PM_BH);
        const uint32_t aAddr = Ap + (uint32_t)((m0 + arow) * 208 + acol16);
        const uint32_t bAddr = Bp + (uint32_t)((NBr + brw) * 208 + bcol16);
        #pragma unroll 1
        for (int kk = 0; kk < 6; kk++) {
            uint32_t a00, a01, a02, a03, a10, a11, a12, a13;
            ldsm_x4(a00, a01, a02, a03, aAddr + kk * 32);
            ldsm_x4(a10, a11, a12, a13, aAddr + 16 * 208 + kk * 32);
            #pragma unroll
            for (int nt = 0; nt < 6; nt++) {
                uint32_t b0, b1;
                ldsm_x2(b0, b1, bAddr + nt * (8 * 208) + kk * 32);
                mma16816(d[0][nt], a00, a01, a02, a03, b0, b1);
                mma16816(d[1][nt], a10, a11, a12, a13, b0, b1);
            }
        }
    }

    const int gr  = l >> 2;
    const int gc2 = (l & 3) * 2;
    float* ob = out + (size_t)tile * (128 * 96);
    #pragma unroll
    for (int mt = 0; mt < 2; mt++) {
        int r0 = m0 + mt * 16 + gr;
        #pragma unroll
        for (int nt = 0; nt < 6; nt++) {
            int n0 = NBr + nt * 8 + gc2;
            float b0 = brow[n0];
            float b1 = brow[n0 + 1];
            *(float2*)(ob + r0 * 96 + n0)       = make_float2(d[mt][nt][0] + b0, d[mt][nt][1] + b1);
            *(float2*)(ob + (r0 + 8) * 96 + n0) = make_float2(d[mt][nt][2] + b0, d[mt][nt][3] + b1);
        }
    }
}

// ---------------------------------------------------------------------------
extern "C" void kernel_launch(void* const* d_in, const int* in_sizes, int n_in,
                              void* d_out, int out_size)
{
    (void)in_sizes; (void)n_in; (void)out_size;
    const float* x        = (const float*)d_in[0];
    const float* w_qkv    = (const float*)d_in[1];
    const float* b_qkv    = (const float*)d_in[2];
    const float* w_proj   = (const float*)d_in[3];
    const float* b_proj   = (const float*)d_in[4];
    const float* rel_bias = (const float*)d_in[5];
    float* out = (float*)d_out;

    cudaFuncSetAttribute(qkv_mma_kernel,  cudaFuncAttributeMaxDynamicSharedMemorySize, SM_TOT);
    cudaFuncSetAttribute(proj_mma_kernel, cudaFuncAttributeMaxDynamicSharedMemorySize, PM_TOT);

    prep_kernel<<<1, 256>>>(w_qkv, b_qkv, w_proj);
    qkv_mma_kernel<<<MROWS / QT, 256, SM_TOT>>>(x);
    attn_kernel<<<WTOT / 2, 128>>>(rel_bias);
    proj_mma_kernel<<<MROWS / QT, 256, PM_TOT>>>(b_proj, out);
}